// round 1
// baseline (speedup 1.0000x reference)
#include <cuda_runtime.h>
#include <cuda_bf16.h>
#include <math.h>

#define NN   8192
#define EE   262144
#define DIN  512
#define H1D  256
#define LATD 128

// ---------------- scratch (device globals; no allocation allowed) ----------
__device__ int   g_is64;
__device__ int   g_cnt[NN];
__device__ int   g_off[NN + 1];
__device__ int   g_cur[NN];
__device__ int   g_csr[EE];
__device__ float g_dis[NN];
__device__ float g_hs1[NN * H1D];
__device__ float g_z1 [NN * H1D];
__device__ float g_hs2[NN * LATD];
__device__ float g_z2 [NN * LATD];

// ---------------- graph preprocessing --------------------------------------
__global__ void k_init() {
    int i = blockIdx.x * blockDim.x + threadIdx.x;
    if (i < NN) g_cnt[i] = 0;
    if (i == 0) g_is64 = 1;
}

// Detect int64 vs int32 edge_index: if int64 (values < 2^13), every odd 32-bit
// word is 0. If int32, odd words are random node ids (prob of all-zero ~ 0).
__global__ void k_detect(const int* __restrict__ ei) {
    int i = blockIdx.x * blockDim.x + threadIdx.x;
    if (i < 8192) {
        if (ei[2 * i + 1] != 0) g_is64 = 0;
    }
}

__device__ __forceinline__ int edge_val(const int* ei, int idx) {
    return g_is64 ? ei[2 * idx] : ei[idx];
}

__global__ void k_count(const int* __restrict__ ei) {
    int e = blockIdx.x * blockDim.x + threadIdx.x;
    if (e >= EE) return;
    int c = edge_val(ei, EE + e);
    atomicAdd(&g_cnt[c], 1);
}

// Single-block exclusive scan over 8192 counts; also dis = (deg+2)^-1/2
__global__ void k_scan() {
    __shared__ int ssum[1024];
    int t = threadIdx.x;
    int base = t * 8;
    int loc[8];
    int s = 0;
#pragma unroll
    for (int i = 0; i < 8; i++) { loc[i] = s; s += g_cnt[base + i]; }
    ssum[t] = s;
    __syncthreads();
    for (int d = 1; d < 1024; d <<= 1) {
        int v = (t >= d) ? ssum[t - d] : 0;
        __syncthreads();
        if (t >= d) ssum[t] += v;
        __syncthreads();
    }
    int prev = (t == 0) ? 0 : ssum[t - 1];
#pragma unroll
    for (int i = 0; i < 8; i++) {
        int o = prev + loc[i];
        g_off[base + i] = o;
        g_cur[base + i] = o;
        g_dis[base + i] = rsqrtf((float)(g_cnt[base + i] + 2));
    }
    if (t == 1023) g_off[NN] = ssum[1023];
}

__global__ void k_fill(const int* __restrict__ ei) {
    int e = blockIdx.x * blockDim.x + threadIdx.x;
    if (e >= EE) return;
    int r = edge_val(ei, e);
    int c = edge_val(ei, EE + e);
    int p = atomicAdd(&g_cur[c], 1);
    g_csr[p] = r;
}

// ---------------- generic fp32 GEMM: C = op(A[MxK] @ B[KxN]) ----------------
// BM=BN=128, BK=8, 256 threads, 8x8 per thread. M%128==0, N%128==0, K%8==0.
// epilogue: if scaleRow: *= scaleRow[m]; if bias: += bias[n]
__global__ void __launch_bounds__(256)
k_gemm(const float* __restrict__ A, const float* __restrict__ B,
       float* __restrict__ C, int M, int Ncols, int K,
       const float* __restrict__ scaleRow, const float* __restrict__ bias)
{
    __shared__ __align__(16) float As[8][128];
    __shared__ __align__(16) float Bs[8][128];
    int tid = threadIdx.x;
    int tx = tid & 15;        // 0..15  -> n sub-tile
    int ty = tid >> 4;        // 0..15  -> m sub-tile
    int bm = blockIdx.y * 128;
    int bn = blockIdx.x * 128;

    int a_row = tid >> 1;          // 0..127
    int a_col = (tid & 1) * 4;     // 0 or 4
    int b_row = tid >> 5;          // 0..7
    int b_col = (tid & 31) * 4;    // 0..124

    float acc[8][8];
#pragma unroll
    for (int i = 0; i < 8; i++)
#pragma unroll
        for (int j = 0; j < 8; j++) acc[i][j] = 0.f;

    for (int k0 = 0; k0 < K; k0 += 8) {
        float4 av = *(const float4*)&A[(size_t)(bm + a_row) * K + k0 + a_col];
        As[a_col + 0][a_row] = av.x;
        As[a_col + 1][a_row] = av.y;
        As[a_col + 2][a_row] = av.z;
        As[a_col + 3][a_row] = av.w;
        float4 bv = *(const float4*)&B[(size_t)(k0 + b_row) * Ncols + bn + b_col];
        *(float4*)&Bs[b_row][b_col] = bv;
        __syncthreads();
#pragma unroll
        for (int kk = 0; kk < 8; kk++) {
            float4 a0 = *(const float4*)&As[kk][ty * 8];
            float4 a1 = *(const float4*)&As[kk][ty * 8 + 4];
            float4 b0 = *(const float4*)&Bs[kk][tx * 8];
            float4 b1 = *(const float4*)&Bs[kk][tx * 8 + 4];
            float ar[8] = {a0.x, a0.y, a0.z, a0.w, a1.x, a1.y, a1.z, a1.w};
            float br[8] = {b0.x, b0.y, b0.z, b0.w, b1.x, b1.y, b1.z, b1.w};
#pragma unroll
            for (int i = 0; i < 8; i++)
#pragma unroll
                for (int j = 0; j < 8; j++) acc[i][j] += ar[i] * br[j];
        }
        __syncthreads();
    }

#pragma unroll
    for (int i = 0; i < 8; i++) {
        int m = bm + ty * 8 + i;
        float sc = scaleRow ? scaleRow[m] : 1.f;
#pragma unroll
        for (int j = 0; j < 8; j += 4) {
            int n = bn + tx * 8 + j;
            float4 bb = bias ? *(const float4*)&bias[n] : make_float4(0.f, 0.f, 0.f, 0.f);
            float4 v;
            v.x = acc[i][j + 0] * sc + bb.x;
            v.y = acc[i][j + 1] * sc + bb.y;
            v.z = acc[i][j + 2] * sc + bb.z;
            v.w = acc[i][j + 3] * sc + bb.w;
            *(float4*)&C[(size_t)m * Ncols + n] = v;
        }
    }
}

// ---------------- neighborhood aggregation ---------------------------------
// out[i] = maybe_relu( dis[i] * ( sum_{j in CSR[i]} hs[j] + 2*hs[i] ) + bias )
__global__ void k_agg(const float* __restrict__ hs, const float* __restrict__ bias,
                      float* __restrict__ out, int F, int relu)
{
    __shared__ int sj[256];
    int i = blockIdx.x;
    int f = threadIdx.x;
    float acc = 2.f * hs[(size_t)i * F + f];
    int s = g_off[i], e = g_off[i + 1];
    for (int base = s; base < e; base += blockDim.x) {
        int m = min((int)blockDim.x, e - base);
        __syncthreads();
        if (f < m) sj[f] = g_csr[base + f];
        __syncthreads();
        for (int p = 0; p < m; p++)
            acc += hs[(size_t)sj[p] * F + f];
    }
    float v = g_dis[i] * acc + bias[f];
    out[(size_t)i * F + f] = relu ? fmaxf(v, 0.f) : v;
}

// ---------------- adj = sigmoid(mu @ mu^T), symmetric ----------------------
// 128x128 tile per block; only (bi,bj) with bj>=bi; mirror via smem transpose.
__global__ void __launch_bounds__(256)
k_adj(const float* __restrict__ A, float* __restrict__ C)
{
    __shared__ __align__(16) float sh[32 * 132];   // 16.9 KB, reused
    float (*As)[128] = (float(*)[128])sh;          // 8 x 128
    float (*Bs)[128] = (float(*)[128])(sh + 1024); // 8 x 128

    // decode triangular block index
    int t = blockIdx.x;
    int bi = 0;
    while (t >= 64 - bi) { t -= 64 - bi; bi++; }
    int bj = bi + t;

    int tid = threadIdx.x;
    int tx = tid & 15, ty = tid >> 4;
    int lrow = tid >> 1;
    int lc = (tid & 1) * 4;

    const float* Ai = A + (size_t)(bi * 128) * LATD;
    const float* Aj = A + (size_t)(bj * 128) * LATD;

    float acc[8][8];
#pragma unroll
    for (int i = 0; i < 8; i++)
#pragma unroll
        for (int j = 0; j < 8; j++) acc[i][j] = 0.f;

    for (int k0 = 0; k0 < LATD; k0 += 8) {
        float4 av = *(const float4*)&Ai[(size_t)lrow * LATD + k0 + lc];
        float4 bv = *(const float4*)&Aj[(size_t)lrow * LATD + k0 + lc];
        As[lc + 0][lrow] = av.x; As[lc + 1][lrow] = av.y;
        As[lc + 2][lrow] = av.z; As[lc + 3][lrow] = av.w;
        Bs[lc + 0][lrow] = bv.x; Bs[lc + 1][lrow] = bv.y;
        Bs[lc + 2][lrow] = bv.z; Bs[lc + 3][lrow] = bv.w;
        __syncthreads();
#pragma unroll
        for (int kk = 0; kk < 8; kk++) {
            float4 a0 = *(const float4*)&As[kk][ty * 8];
            float4 a1 = *(const float4*)&As[kk][ty * 8 + 4];
            float4 b0 = *(const float4*)&Bs[kk][tx * 8];
            float4 b1 = *(const float4*)&Bs[kk][tx * 8 + 4];
            float ar[8] = {a0.x, a0.y, a0.z, a0.w, a1.x, a1.y, a1.z, a1.w};
            float br[8] = {b0.x, b0.y, b0.z, b0.w, b1.x, b1.y, b1.z, b1.w};
#pragma unroll
            for (int i = 0; i < 8; i++)
#pragma unroll
                for (int j = 0; j < 8; j++) acc[i][j] += ar[i] * br[j];
        }
        __syncthreads();
    }

    // sigmoid
#pragma unroll
    for (int i = 0; i < 8; i++)
#pragma unroll
        for (int j = 0; j < 8; j++)
            acc[i][j] = 1.f / (1.f + __expf(-acc[i][j]));

    // normal tile store (rows bi, cols bj)
#pragma unroll
    for (int i = 0; i < 8; i++) {
        size_t row = (size_t)(bi * 128 + ty * 8 + i);
        float4 v0 = make_float4(acc[i][0], acc[i][1], acc[i][2], acc[i][3]);
        float4 v1 = make_float4(acc[i][4], acc[i][5], acc[i][6], acc[i][7]);
        *(float4*)&C[row * NN + bj * 128 + tx * 8    ] = v0;
        *(float4*)&C[row * NN + bj * 128 + tx * 8 + 4] = v1;
    }

    // mirrored tile (rows bj, cols bi) via staged transpose
    if (bi != bj) {
        float (*T)[132] = (float(*)[132])sh;
        int lane = tid & 31, w = tid >> 5;
#pragma unroll 1
        for (int ch = 0; ch < 4; ch++) {
            __syncthreads();
            if ((tx >> 2) == ch) {
                int txl = tx & 3;
#pragma unroll
                for (int j = 0; j < 8; j++)
#pragma unroll
                    for (int i = 0; i < 8; i++)
                        T[txl * 8 + j][ty * 8 + i] = acc[i][j];
            }
            __syncthreads();
#pragma unroll
            for (int rr = 0; rr < 4; rr++) {
                int r = w + rr * 8;   // 0..31
                float4 v = *(const float4*)&T[r][lane * 4];
                *(float4*)&C[(size_t)(bj * 128 + ch * 32 + r) * NN + bi * 128 + lane * 4] = v;
            }
        }
    }
}

// ---------------- launch ----------------------------------------------------
extern "C" void kernel_launch(void* const* d_in, const int* in_sizes, int n_in,
                              void* d_out, int out_size)
{
    const float* x   = (const float*)d_in[0];
    const int*   ei  = (const int*)d_in[1];   // width auto-detected on device
    const float* W1  = (const float*)d_in[2];
    const float* b1  = (const float*)d_in[3];
    const float* W2  = (const float*)d_in[4];
    const float* b2  = (const float*)d_in[5];
    const float* Wmu = (const float*)d_in[6];
    const float* bmu = (const float*)d_in[7];
    const float* Wlv = (const float*)d_in[8];
    const float* blv = (const float*)d_in[9];

    float* out = (float*)d_out;
    float* mu  = out + (size_t)NN * NN;
    float* lv  = mu + (size_t)NN * LATD;

    float *p_hs1, *p_z1, *p_hs2, *p_z2, *p_dis;
    cudaGetSymbolAddress((void**)&p_hs1, g_hs1);
    cudaGetSymbolAddress((void**)&p_z1,  g_z1);
    cudaGetSymbolAddress((void**)&p_hs2, g_hs2);
    cudaGetSymbolAddress((void**)&p_z2,  g_z2);
    cudaGetSymbolAddress((void**)&p_dis, g_dis);

    k_init  <<<8, 1024>>>();
    k_detect<<<32, 256>>>(ei);
    k_count <<<EE / 256, 256>>>(ei);
    k_scan  <<<1, 1024>>>();
    k_fill  <<<EE / 256, 256>>>(ei);

    // layer 1: hs1 = dis * (x @ W1)
    k_gemm<<<dim3(H1D / 128, NN / 128), 256>>>(x, W1, p_hs1, NN, H1D, DIN, p_dis, nullptr);
    k_agg <<<NN, H1D>>>(p_hs1, b1, p_z1, H1D, 1);

    // layer 2: hs2 = dis * (z1 @ W2)
    k_gemm<<<dim3(LATD / 128, NN / 128), 256>>>(p_z1, W2, p_hs2, NN, LATD, H1D, p_dis, nullptr);
    k_agg <<<NN, LATD>>>(p_hs2, b2, p_z2, LATD, 0);

    // heads
    k_gemm<<<dim3(LATD / 128, NN / 128), 256>>>(p_z2, Wmu, mu, NN, LATD, LATD, nullptr, bmu);
    k_gemm<<<dim3(LATD / 128, NN / 128), 256>>>(p_z2, Wlv, lv, NN, LATD, LATD, nullptr, blv);

    // adj = sigmoid(mu @ mu^T), symmetric: 64*65/2 = 2080 tile-blocks
    k_adj<<<2080, 256>>>(mu, out);
}

// round 3
// speedup vs baseline: 1.3944x; 1.3944x over previous
#include <cuda_runtime.h>
#include <cuda_bf16.h>
#include <math.h>
#include <stdint.h>

#define NN   8192
#define EE   262144
#define DIN  512
#define H1D  256
#define LATD 128

// ---------------- scratch (device globals; no allocation allowed) ----------
__device__ int   g_is64;
__device__ int   g_cnt[NN];
__device__ int   g_off[NN + 1];
__device__ int   g_cur[NN];
__device__ int   g_csr[EE];
__device__ float g_dis[NN];
__device__ float g_hs1[NN * H1D];
__device__ float g_z1 [NN * H1D];
__device__ float g_hs2[NN * LATD];
__device__ float g_z2 [NN * LATD];
__device__ __nv_bfloat16 g_muh[NN * LATD];
__device__ __nv_bfloat16 g_mul[NN * LATD];

// ---------------- graph preprocessing --------------------------------------
__global__ void k_init() {
    int i = blockIdx.x * blockDim.x + threadIdx.x;
    if (i < NN) g_cnt[i] = 0;
    if (i == 0) g_is64 = 1;
}

__global__ void k_detect(const int* __restrict__ ei) {
    int i = blockIdx.x * blockDim.x + threadIdx.x;
    if (i < 8192) {
        if (ei[2 * i + 1] != 0) g_is64 = 0;
    }
}

__device__ __forceinline__ int edge_val(const int* ei, int idx) {
    return g_is64 ? ei[2 * idx] : ei[idx];
}

__global__ void k_count(const int* __restrict__ ei) {
    int e = blockIdx.x * blockDim.x + threadIdx.x;
    if (e >= EE) return;
    int c = edge_val(ei, EE + e);
    atomicAdd(&g_cnt[c], 1);
}

// 256-thread scan over 8192 counts via warp shuffles; also dis = (deg+2)^-1/2
__global__ void k_scan() {
    __shared__ int wsum[8];
    int t = threadIdx.x;
    int lane = t & 31;
    int base = t * 32;
    int loc[32];
    int s = 0;
#pragma unroll
    for (int i = 0; i < 32; i++) { loc[i] = s; s += g_cnt[base + i]; }
    int v = s;
#pragma unroll
    for (int d = 1; d < 32; d <<= 1) {
        int u = __shfl_up_sync(0xffffffff, v, d);
        if (lane >= d) v += u;
    }
    if (lane == 31) wsum[t >> 5] = v;
    __syncthreads();
    if (t < 8) {
        int w = wsum[t];
#pragma unroll
        for (int d = 1; d < 8; d <<= 1) {
            int u = __shfl_up_sync(0xff, w, d);
            if (t >= d) w += u;
        }
        wsum[t] = w;
    }
    __syncthreads();
    int warpoff = (t >> 5) ? wsum[(t >> 5) - 1] : 0;
    int excl = warpoff + v - s;
#pragma unroll
    for (int i = 0; i < 32; i++) {
        int o = excl + loc[i];
        g_off[base + i] = o;
        g_cur[base + i] = o;
        g_dis[base + i] = rsqrtf((float)(g_cnt[base + i] + 2));
    }
    if (t == 255) g_off[NN] = warpoff + v;
}

__global__ void k_fill(const int* __restrict__ ei) {
    int e = blockIdx.x * blockDim.x + threadIdx.x;
    if (e >= EE) return;
    int r = edge_val(ei, e);
    int c = edge_val(ei, EE + e);
    int p = atomicAdd(&g_cur[c], 1);
    g_csr[p] = r;
}

// ---------------- generic fp32 GEMM (SIMT) ----------------------------------
__global__ void __launch_bounds__(256)
k_gemm(const float* __restrict__ A, const float* __restrict__ B,
       float* __restrict__ C, int M, int Ncols, int K,
       const float* __restrict__ scaleRow, const float* __restrict__ bias)
{
    __shared__ __align__(16) float As[8][128];
    __shared__ __align__(16) float Bs[8][128];
    int tid = threadIdx.x;
    int tx = tid & 15;
    int ty = tid >> 4;
    int bm = blockIdx.y * 128;
    int bn = blockIdx.x * 128;

    int a_row = tid >> 1;
    int a_col = (tid & 1) * 4;
    int b_row = tid >> 5;
    int b_col = (tid & 31) * 4;

    float acc[8][8];
#pragma unroll
    for (int i = 0; i < 8; i++)
#pragma unroll
        for (int j = 0; j < 8; j++) acc[i][j] = 0.f;

    for (int k0 = 0; k0 < K; k0 += 8) {
        float4 av = *(const float4*)&A[(size_t)(bm + a_row) * K + k0 + a_col];
        As[a_col + 0][a_row] = av.x;
        As[a_col + 1][a_row] = av.y;
        As[a_col + 2][a_row] = av.z;
        As[a_col + 3][a_row] = av.w;
        float4 bv = *(const float4*)&B[(size_t)(k0 + b_row) * Ncols + bn + b_col];
        *(float4*)&Bs[b_row][b_col] = bv;
        __syncthreads();
#pragma unroll
        for (int kk = 0; kk < 8; kk++) {
            float4 a0 = *(const float4*)&As[kk][ty * 8];
            float4 a1 = *(const float4*)&As[kk][ty * 8 + 4];
            float4 b0 = *(const float4*)&Bs[kk][tx * 8];
            float4 b1 = *(const float4*)&Bs[kk][tx * 8 + 4];
            float ar[8] = {a0.x, a0.y, a0.z, a0.w, a1.x, a1.y, a1.z, a1.w};
            float br[8] = {b0.x, b0.y, b0.z, b0.w, b1.x, b1.y, b1.z, b1.w};
#pragma unroll
            for (int i = 0; i < 8; i++)
#pragma unroll
                for (int j = 0; j < 8; j++) acc[i][j] += ar[i] * br[j];
        }
        __syncthreads();
    }

#pragma unroll
    for (int i = 0; i < 8; i++) {
        int m = bm + ty * 8 + i;
        float sc = scaleRow ? scaleRow[m] : 1.f;
#pragma unroll
        for (int j = 0; j < 8; j += 4) {
            int n = bn + tx * 8 + j;
            float4 bb = bias ? *(const float4*)&bias[n] : make_float4(0.f, 0.f, 0.f, 0.f);
            float4 v;
            v.x = acc[i][j + 0] * sc + bb.x;
            v.y = acc[i][j + 1] * sc + bb.y;
            v.z = acc[i][j + 2] * sc + bb.z;
            v.w = acc[i][j + 3] * sc + bb.w;
            *(float4*)&C[(size_t)m * Ncols + n] = v;
        }
    }
}

// ---------------- neighborhood aggregation ---------------------------------
__global__ void k_agg(const float* __restrict__ hs, const float* __restrict__ bias,
                      float* __restrict__ out, int F, int relu)
{
    __shared__ int sj[256];
    int i = blockIdx.x;
    int f = threadIdx.x;
    float acc = 2.f * hs[(size_t)i * F + f];
    int s = g_off[i], e = g_off[i + 1];
    for (int base = s; base < e; base += blockDim.x) {
        int m = min((int)blockDim.x, e - base);
        __syncthreads();
        if (f < m) sj[f] = g_csr[base + f];
        __syncthreads();
        for (int p = 0; p < m; p++)
            acc += hs[(size_t)sj[p] * F + f];
    }
    float v = g_dis[i] * acc + bias[f];
    out[(size_t)i * F + f] = relu ? fmaxf(v, 0.f) : v;
}

// ---------------- split mu -> bf16 hi/lo planes ----------------------------
__global__ void k_split(const float* __restrict__ mu) {
    int i = blockIdx.x * blockDim.x + threadIdx.x;   // float4 index
    float4 v = ((const float4*)mu)[i];
    __nv_bfloat16 h0 = __float2bfloat16(v.x);
    __nv_bfloat16 h1 = __float2bfloat16(v.y);
    __nv_bfloat16 h2 = __float2bfloat16(v.z);
    __nv_bfloat16 h3 = __float2bfloat16(v.w);
    __nv_bfloat16 l0 = __float2bfloat16(v.x - __bfloat162float(h0));
    __nv_bfloat16 l1 = __float2bfloat16(v.y - __bfloat162float(h1));
    __nv_bfloat16 l2 = __float2bfloat16(v.z - __bfloat162float(h2));
    __nv_bfloat16 l3 = __float2bfloat16(v.w - __bfloat162float(h3));
    uint2 hv, lv;
    hv.x = ((uint32_t)__bfloat16_as_ushort(h1) << 16) | __bfloat16_as_ushort(h0);
    hv.y = ((uint32_t)__bfloat16_as_ushort(h3) << 16) | __bfloat16_as_ushort(h2);
    lv.x = ((uint32_t)__bfloat16_as_ushort(l1) << 16) | __bfloat16_as_ushort(l0);
    lv.y = ((uint32_t)__bfloat16_as_ushort(l3) << 16) | __bfloat16_as_ushort(l2);
    ((uint2*)g_muh)[i] = hv;
    ((uint2*)g_mul)[i] = lv;
}

// ---------------- mma.sync helpers ------------------------------------------
__device__ __forceinline__ uint32_t smem_u32(const void* p) {
    uint32_t a;
    asm("{ .reg .u64 t; cvta.to.shared.u64 t, %1; cvt.u32.u64 %0, t; }" : "=r"(a) : "l"(p));
    return a;
}

__device__ __forceinline__ void ldsm_x4(uint32_t* r, uint32_t addr) {
    asm volatile("ldmatrix.sync.aligned.m8n8.x4.shared.b16 {%0,%1,%2,%3}, [%4];"
                 : "=r"(r[0]), "=r"(r[1]), "=r"(r[2]), "=r"(r[3]) : "r"(addr));
}

__device__ __forceinline__ void mma16816(float* d, const uint32_t* a, const uint32_t* b) {
    asm volatile("mma.sync.aligned.m16n8k16.row.col.f32.bf16.bf16.f32 "
                 "{%0,%1,%2,%3}, {%4,%5,%6,%7}, {%8,%9}, {%0,%1,%2,%3};"
                 : "+f"(d[0]), "+f"(d[1]), "+f"(d[2]), "+f"(d[3])
                 : "r"(a[0]), "r"(a[1]), "r"(a[2]), "r"(a[3]), "r"(b[0]), "r"(b[1]));
}

// ---------------- adj = sigmoid(mu @ mu^T) via HMMA bf16-split ---------------
// CTA: 128x128 tile, triangular (bj>=bi), mirror via smem transpose.
// C = Ah*Bh^T + Ah*Bl^T + Al*Bh^T  (fp32 accum in fragments).
// smem: two tiles, pitch 136 bf16 (272B) -> conflict-free ldmatrix.
#define TP       136
#define TILE_B   (128 * TP * 2)          // 34816
#define ADJ_SMEM (2 * TILE_B)            // 69632

__device__ __forceinline__ void load_tile(const __nv_bfloat16* g, int rowblk, char* s) {
    const uint4* src = (const uint4*)(g + (size_t)rowblk * 128 * 128);
    int tid = threadIdx.x;
#pragma unroll
    for (int q = 0; q < 8; q++) {
        int idx = q * 256 + tid;
        int r = idx >> 4, c = idx & 15;
        *(uint4*)(s + r * (TP * 2) + c * 16) = src[idx];
    }
}

__device__ __forceinline__ void mma_pass(uint32_t sA, uint32_t sB, int m_w, int n_w,
                                         float d[2][8][4], int lane) {
    uint32_t a_base = sA + ((m_w + (lane & 15)) * TP + (lane >> 4) * 8) * 2;
    int bmi = lane >> 3;                   // 0..3
    uint32_t b_base = sB + ((n_w + ((bmi >> 1) * 8) + (lane & 7)) * TP + (bmi & 1) * 8) * 2;
#pragma unroll
    for (int kk = 0; kk < 8; kk++) {
        int k0 = kk * 16;
        uint32_t a[2][4];
        ldsm_x4(a[0], a_base + k0 * 2);
        ldsm_x4(a[1], a_base + (16 * TP + k0) * 2);
        uint32_t b[4][4];
#pragma unroll
        for (int np = 0; np < 4; np++)
            ldsm_x4(b[np], b_base + (np * 16 * TP + k0) * 2);
#pragma unroll
        for (int mi = 0; mi < 2; mi++)
#pragma unroll
            for (int np = 0; np < 4; np++) {
                mma16816(d[mi][np * 2 + 0], a[mi], &b[np][0]);
                mma16816(d[mi][np * 2 + 1], a[mi], &b[np][2]);
            }
    }
}

__global__ void __launch_bounds__(256, 2)
k_adj_mma(const __nv_bfloat16* __restrict__ Ah, const __nv_bfloat16* __restrict__ Al,
          float* __restrict__ C)
{
    extern __shared__ __align__(16) char smem[];
    char* sA = smem;
    char* sB = smem + TILE_B;
    uint32_t sAu = smem_u32(sA), sBu = smem_u32(sB);

    int tid = threadIdx.x, wid = tid >> 5, lane = tid & 31;
    int m_w = (wid & 3) * 32, n_w = (wid >> 2) * 64;

    // triangular block decode
    int t = blockIdx.x, bi = 0;
    while (t >= 64 - bi) { t -= 64 - bi; bi++; }
    int bj = bi + t;

    float d[2][8][4];
#pragma unroll
    for (int mi = 0; mi < 2; mi++)
#pragma unroll
        for (int ni = 0; ni < 8; ni++)
#pragma unroll
            for (int q = 0; q < 4; q++) d[mi][ni][q] = 0.f;

    // pass 0: Ah x Bh
    load_tile(Ah, bi, sA);
    load_tile(Ah, bj, sB);
    __syncthreads();
    mma_pass(sAu, sBu, m_w, n_w, d, lane);
    __syncthreads();
    // pass 1: Ah x Bl
    load_tile(Al, bj, sB);
    __syncthreads();
    mma_pass(sAu, sBu, m_w, n_w, d, lane);
    __syncthreads();
    // pass 2: Al x Bh
    load_tile(Al, bi, sA);
    load_tile(Ah, bj, sB);
    __syncthreads();
    mma_pass(sAu, sBu, m_w, n_w, d, lane);

    // sigmoid
#pragma unroll
    for (int mi = 0; mi < 2; mi++)
#pragma unroll
        for (int ni = 0; ni < 8; ni++)
#pragma unroll
            for (int q = 0; q < 4; q++)
                d[mi][ni][q] = 1.f / (1.f + __expf(-d[mi][ni][q]));

    int g = lane >> 2, tq = lane & 3;

    // normal tile store (rows bi, cols bj): 32B fully-written sectors
#pragma unroll
    for (int mi = 0; mi < 2; mi++) {
        size_t r0 = (size_t)(bi * 128 + m_w + mi * 16 + g);
#pragma unroll
        for (int ni = 0; ni < 8; ni++) {
            size_t cc = (size_t)(bj * 128 + n_w + ni * 8 + tq * 2);
            *(float2*)&C[r0 * NN + cc]       = make_float2(d[mi][ni][0], d[mi][ni][1]);
            *(float2*)&C[(r0 + 8) * NN + cc] = make_float2(d[mi][ni][2], d[mi][ni][3]);
        }
    }

    // mirror tile via smem transpose (pitch 129: conflict-free both phases)
    if (bi != bj) {
        __syncthreads();
        float* T = (float*)smem;
#pragma unroll
        for (int mi = 0; mi < 2; mi++) {
            int r = m_w + mi * 16 + g;
#pragma unroll
            for (int ni = 0; ni < 8; ni++) {
                int c = n_w + ni * 8 + tq * 2;
                T[r * 129 + c]           = d[mi][ni][0];
                T[r * 129 + c + 1]       = d[mi][ni][1];
                T[(r + 8) * 129 + c]     = d[mi][ni][2];
                T[(r + 8) * 129 + c + 1] = d[mi][ni][3];
            }
        }
        __syncthreads();
#pragma unroll
        for (int q = 0; q < 64; q++) {
            int lin = q * 256 + tid;
            int cc = lin >> 7, rr = lin & 127;
            C[(size_t)(bj * 128 + cc) * NN + bi * 128 + rr] = T[rr * 129 + cc];
        }
    }
}

// ---------------- launch ----------------------------------------------------
extern "C" void kernel_launch(void* const* d_in, const int* in_sizes, int n_in,
                              void* d_out, int out_size)
{
    const float* x   = (const float*)d_in[0];
    const int*   ei  = (const int*)d_in[1];   // width auto-detected on device
    const float* W1  = (const float*)d_in[2];
    const float* b1  = (const float*)d_in[3];
    const float* W2  = (const float*)d_in[4];
    const float* b2  = (const float*)d_in[5];
    const float* Wmu = (const float*)d_in[6];
    const float* bmu = (const float*)d_in[7];
    const float* Wlv = (const float*)d_in[8];
    const float* blv = (const float*)d_in[9];

    float* out = (float*)d_out;
    float* mu  = out + (size_t)NN * NN;
    float* lv  = mu + (size_t)NN * LATD;

    float *p_hs1, *p_z1, *p_hs2, *p_z2, *p_dis;
    __nv_bfloat16 *p_muh, *p_mul;
    cudaGetSymbolAddress((void**)&p_hs1, g_hs1);
    cudaGetSymbolAddress((void**)&p_z1,  g_z1);
    cudaGetSymbolAddress((void**)&p_hs2, g_hs2);
    cudaGetSymbolAddress((void**)&p_z2,  g_z2);
    cudaGetSymbolAddress((void**)&p_dis, g_dis);
    cudaGetSymbolAddress((void**)&p_muh, g_muh);
    cudaGetSymbolAddress((void**)&p_mul, g_mul);

    cudaFuncSetAttribute(k_adj_mma, cudaFuncAttributeMaxDynamicSharedMemorySize, ADJ_SMEM);

    k_init  <<<8, 1024>>>();
    k_detect<<<32, 256>>>(ei);
    k_count <<<EE / 256, 256>>>(ei);
    k_scan  <<<1, 256>>>();
    k_fill  <<<EE / 256, 256>>>(ei);

    // layer 1: hs1 = dis * (x @ W1)
    k_gemm<<<dim3(H1D / 128, NN / 128), 256>>>(x, W1, p_hs1, NN, H1D, DIN, p_dis, nullptr);
    k_agg <<<NN, H1D>>>(p_hs1, b1, p_z1, H1D, 1);

    // layer 2: hs2 = dis * (z1 @ W2)
    k_gemm<<<dim3(LATD / 128, NN / 128), 256>>>(p_z1, W2, p_hs2, NN, LATD, H1D, p_dis, nullptr);
    k_agg <<<NN, LATD>>>(p_hs2, b2, p_z2, LATD, 0);

    // heads
    k_gemm<<<dim3(LATD / 128, NN / 128), 256>>>(p_z2, Wmu, mu, NN, LATD, LATD, nullptr, bmu);
    k_gemm<<<dim3(LATD / 128, NN / 128), 256>>>(p_z2, Wlv, lv, NN, LATD, LATD, nullptr, blv);

    // adj = sigmoid(mu @ mu^T) on tensor cores (bf16-split, fp32 accum)
    k_split<<<(NN * LATD / 4) / 256, 256>>>(mu);
    k_adj_mma<<<2080, 256, ADJ_SMEM>>>(p_muh, p_mul, out);
}

// round 6
// speedup vs baseline: 1.8810x; 1.3490x over previous
#include <cuda_runtime.h>
#include <cuda_bf16.h>
#include <math.h>
#include <stdint.h>

#define NN   8192
#define EE   262144
#define DIN  512
#define H1D  256
#define LATD 128

// ---------------- scratch (device globals; no allocation allowed) ----------
__device__ int   g_is64;
__device__ int   g_cnt[NN];
__device__ int   g_off[NN + 1];
__device__ int   g_cur[NN];
__device__ int   g_csr[EE];
__device__ float g_dis[NN];
__device__ float g_hs1[NN * H1D];
__device__ float g_hs2[NN * LATD];
__device__ __nv_bfloat16 g_xh [NN * DIN],  g_xl [NN * DIN];
__device__ __nv_bfloat16 g_z1h[NN * H1D],  g_z1l[NN * H1D];
__device__ __nv_bfloat16 g_z2h[NN * LATD], g_z2l[NN * LATD];
__device__ __nv_bfloat16 g_muh[NN * LATD], g_mul[NN * LATD];
__device__ __nv_bfloat16 g_w1h[H1D * DIN],  g_w1l[H1D * DIN];    // W1^T planes
__device__ __nv_bfloat16 g_w2h[LATD * H1D], g_w2l[LATD * H1D];   // W2^T planes
__device__ __nv_bfloat16 g_whh[2 * LATD * LATD], g_whl[2 * LATD * LATD]; // [Wmu|Wlv]^T

// ---------------- graph preprocessing --------------------------------------
__global__ void k_init() {
    int i = blockIdx.x * blockDim.x + threadIdx.x;
    if (i < NN) g_cnt[i] = 0;
    if (i == 0) g_is64 = 1;
}

__global__ void k_detect(const int* __restrict__ ei) {
    int i = blockIdx.x * blockDim.x + threadIdx.x;
    if (i < 8192) {
        if (ei[2 * i + 1] != 0) g_is64 = 0;
    }
}

__device__ __forceinline__ int edge_val(const int* ei, int idx) {
    return g_is64 ? ei[2 * idx] : ei[idx];
}

__global__ void k_count(const int* __restrict__ ei) {
    int e = blockIdx.x * blockDim.x + threadIdx.x;
    if (e >= EE) return;
    int c = edge_val(ei, EE + e);
    atomicAdd(&g_cnt[c], 1);
}

// 1024 threads x 8 counts each; shuffle scan; also dis = (deg+2)^-1/2
__global__ void k_scan() {
    __shared__ int wsum[32];
    int t = threadIdx.x, lane = t & 31, w = t >> 5;
    int base = t * 8;
    int loc[8];
    int s = 0;
#pragma unroll
    for (int i = 0; i < 8; i++) { loc[i] = s; s += g_cnt[base + i]; }
    int v = s;
#pragma unroll
    for (int d = 1; d < 32; d <<= 1) {
        int u = __shfl_up_sync(0xffffffff, v, d);
        if (lane >= d) v += u;
    }
    if (lane == 31) wsum[w] = v;
    __syncthreads();
    if (t < 32) {
        int ww = wsum[t];
#pragma unroll
        for (int d = 1; d < 32; d <<= 1) {
            int u = __shfl_up_sync(0xffffffff, ww, d);
            if (t >= d) ww += u;
        }
        wsum[t] = ww;
    }
    __syncthreads();
    int woff = w ? wsum[w - 1] : 0;
    int excl = woff + v - s;
#pragma unroll
    for (int i = 0; i < 8; i++) {
        int o = excl + loc[i];
        g_off[base + i] = o;
        g_cur[base + i] = o;
        g_dis[base + i] = rsqrtf((float)(g_cnt[base + i] + 2));
    }
    if (t == 1023) g_off[NN] = woff + v;
}

__global__ void k_fill(const int* __restrict__ ei) {
    int e = blockIdx.x * blockDim.x + threadIdx.x;
    if (e >= EE) return;
    int r = edge_val(ei, e);
    int c = edge_val(ei, EE + e);
    int p = atomicAdd(&g_cur[c], 1);
    g_csr[p] = r;
}

// ---------------- split helpers ---------------------------------------------
__device__ __forceinline__ void split1(float v, __nv_bfloat16& h, __nv_bfloat16& l) {
    h = __float2bfloat16(v);
    l = __float2bfloat16(v - __bfloat162float(h));
}

// split fp32 array (float4 granularity) into two bf16 planes
__global__ void k_split(const float* __restrict__ src,
                        __nv_bfloat16* __restrict__ ph, __nv_bfloat16* __restrict__ pl) {
    int i = blockIdx.x * blockDim.x + threadIdx.x;
    float4 v = ((const float4*)src)[i];
    __nv_bfloat16 h0, h1, h2, h3, l0, l1, l2, l3;
    split1(v.x, h0, l0); split1(v.y, h1, l1); split1(v.z, h2, l2); split1(v.w, h3, l3);
    uint2 hv, lv;
    hv.x = ((uint32_t)__bfloat16_as_ushort(h1) << 16) | __bfloat16_as_ushort(h0);
    hv.y = ((uint32_t)__bfloat16_as_ushort(h3) << 16) | __bfloat16_as_ushort(h2);
    lv.x = ((uint32_t)__bfloat16_as_ushort(l1) << 16) | __bfloat16_as_ushort(l0);
    lv.y = ((uint32_t)__bfloat16_as_ushort(l3) << 16) | __bfloat16_as_ushort(l2);
    ((uint2*)ph)[i] = hv;
    ((uint2*)pl)[i] = lv;
}

// W [Kdim x Ndim] row-major -> out planes [Ndim x Kdim] (transposed)
__global__ void k_wsplit(const float* __restrict__ W,
                         __nv_bfloat16* __restrict__ outh, __nv_bfloat16* __restrict__ outl,
                         int Kdim, int Ndim) {
    int idx = blockIdx.x * blockDim.x + threadIdx.x;
    if (idx >= Kdim * Ndim) return;
    int k = idx / Ndim, n = idx % Ndim;
    __nv_bfloat16 h, l;
    split1(W[idx], h, l);
    outh[(size_t)n * Kdim + k] = h;
    outl[(size_t)n * Kdim + k] = l;
}

// ---------------- neighborhood aggregation (emits bf16 planes) --------------
__global__ void k_agg(const float* __restrict__ hs, const float* __restrict__ bias,
                      __nv_bfloat16* __restrict__ zh, __nv_bfloat16* __restrict__ zl,
                      int F, int relu)
{
    __shared__ int sj[256];
    int i = blockIdx.x;
    int f = threadIdx.x;
    float acc = 2.f * hs[(size_t)i * F + f];
    int s = g_off[i], e = g_off[i + 1];
    for (int base = s; base < e; base += blockDim.x) {
        int m = min((int)blockDim.x, e - base);
        __syncthreads();
        if (f < m) sj[f] = g_csr[base + f];
        __syncthreads();
        for (int p = 0; p < m; p++)
            acc += hs[(size_t)sj[p] * F + f];
    }
    float v = g_dis[i] * acc + bias[f];
    if (relu) v = fmaxf(v, 0.f);
    __nv_bfloat16 h, l;
    split1(v, h, l);
    zh[(size_t)i * F + f] = h;
    zl[(size_t)i * F + f] = l;
}

// ---------------- mma.sync helpers ------------------------------------------
__device__ __forceinline__ uint32_t smem_u32(const void* p) {
    uint32_t a;
    asm("{ .reg .u64 t; cvta.to.shared.u64 t, %1; cvt.u32.u64 %0, t; }" : "=r"(a) : "l"(p));
    return a;
}

__device__ __forceinline__ void ldsm_x4(uint32_t* r, uint32_t addr) {
    asm volatile("ldmatrix.sync.aligned.m8n8.x4.shared.b16 {%0,%1,%2,%3}, [%4];"
                 : "=r"(r[0]), "=r"(r[1]), "=r"(r[2]), "=r"(r[3]) : "r"(addr));
}

__device__ __forceinline__ void mma16816(float* d, const uint32_t* a, const uint32_t* b) {
    asm volatile("mma.sync.aligned.m16n8k16.row.col.f32.bf16.bf16.f32 "
                 "{%0,%1,%2,%3}, {%4,%5,%6,%7}, {%8,%9}, {%0,%1,%2,%3};"
                 : "+f"(d[0]), "+f"(d[1]), "+f"(d[2]), "+f"(d[3])
                 : "r"(a[0]), "r"(a[1]), "r"(a[2]), "r"(a[3]), "r"(b[0]), "r"(b[1]));
}

#define TP       136
#define TP2      (TP * 2)
#define TILE_B   (128 * TP2)             // 34816
#define ADJ_SMEM (2 * TILE_B)            // 69632
#define GEMM_SMEM (4 * TILE_B)           // 139264

// one warp: 32(m) x 64(n) sub-tile, 8 k-steps over a 128-wide chunk
__device__ __forceinline__ void mma_pass(uint32_t sA, uint32_t sB, int m_w, int n_w,
                                         float d[2][8][4], int lane) {
    uint32_t a_base = sA + ((m_w + (lane & 15)) * TP + (lane >> 4) * 8) * 2;
    int bmi = lane >> 3;
    uint32_t b_base = sB + ((n_w + ((bmi >> 1) * 8) + (lane & 7)) * TP + (bmi & 1) * 8) * 2;
#pragma unroll
    for (int kk = 0; kk < 8; kk++) {
        int k0 = kk * 16;
        uint32_t a[2][4];
        ldsm_x4(a[0], a_base + k0 * 2);
        ldsm_x4(a[1], a_base + (16 * TP + k0) * 2);
        uint32_t b[4][4];
#pragma unroll
        for (int np = 0; np < 4; np++)
            ldsm_x4(b[np], b_base + (np * 16 * TP + k0) * 2);
#pragma unroll
        for (int mi = 0; mi < 2; mi++)
#pragma unroll
            for (int np = 0; np < 4; np++) {
                mma16816(d[mi][np * 2 + 0], a[mi], &b[np][0]);
                mma16816(d[mi][np * 2 + 1], a[mi], &b[np][2]);
            }
    }
}

// load 128x128 bf16 tile (global row-major, row length K, chunk offset kc)
__device__ __forceinline__ void load_tile_k(const __nv_bfloat16* g, int row0, int K,
                                            int kc, char* s) {
    const __nv_bfloat16* base = g + (size_t)row0 * K + kc;
    int tid = threadIdx.x;
#pragma unroll
    for (int q = 0; q < 8; q++) {
        int idx = q * 256 + tid;
        int r = idx >> 4, c = idx & 15;
        *(uint4*)(s + r * TP2 + c * 16) = *(const uint4*)(base + (size_t)r * K + c * 8);
    }
}

// ---------------- unified bf16-split HMMA GEMM -------------------------------
// C[M x Ncols] = (Ah+Al)[M x K] @ (Bh+Bl)[Ncols x K]^T  (3-pass, fp32 accum)
// layer mode (head==0): Cout = scaleRow[m] * C
// head mode  (head==1): blockIdx.x==0 -> mu (bias bmu, fp32 + bf16 planes)
//                       blockIdx.x==1 -> lv (bias blv, fp32)
__global__ void __launch_bounds__(256, 1)
k_gemm_tc(const __nv_bfloat16* __restrict__ Ah, const __nv_bfloat16* __restrict__ Al,
          const __nv_bfloat16* __restrict__ Bh, const __nv_bfloat16* __restrict__ Bl,
          int K, int Ncols,
          float* __restrict__ Cout, const float* __restrict__ scaleRow,
          int head,
          float* __restrict__ muF, float* __restrict__ lvF,
          const float* __restrict__ bmu, const float* __restrict__ blv,
          __nv_bfloat16* __restrict__ ph, __nv_bfloat16* __restrict__ pl)
{
    extern __shared__ __align__(16) char smem[];
    char* sAh = smem;
    char* sAl = smem + TILE_B;
    char* sBh = smem + 2 * TILE_B;
    char* sBl = smem + 3 * TILE_B;
    uint32_t uAh = smem_u32(sAh), uAl = smem_u32(sAl);
    uint32_t uBh = smem_u32(sBh), uBl = smem_u32(sBl);

    int tid = threadIdx.x, wid = tid >> 5, lane = tid & 31;
    int m_w = (wid & 3) * 32, n_w = (wid >> 2) * 64;
    int bm = blockIdx.y * 128, bn = blockIdx.x * 128;

    float d[2][8][4];
#pragma unroll
    for (int mi = 0; mi < 2; mi++)
#pragma unroll
        for (int ni = 0; ni < 8; ni++)
#pragma unroll
            for (int q = 0; q < 4; q++) d[mi][ni][q] = 0.f;

    for (int kc = 0; kc < K; kc += 128) {
        load_tile_k(Ah, bm, K, kc, sAh);
        load_tile_k(Al, bm, K, kc, sAl);
        load_tile_k(Bh, bn, K, kc, sBh);
        load_tile_k(Bl, bn, K, kc, sBl);
        __syncthreads();
        mma_pass(uAh, uBh, m_w, n_w, d, lane);
        mma_pass(uAh, uBl, m_w, n_w, d, lane);
        mma_pass(uAl, uBh, m_w, n_w, d, lane);
        __syncthreads();
    }

    int g4 = lane >> 2, tq = lane & 3;
    if (!head) {
#pragma unroll
        for (int mi = 0; mi < 2; mi++) {
            int r0 = bm + m_w + mi * 16 + g4;
            float s0 = scaleRow[r0], s1 = scaleRow[r0 + 8];
#pragma unroll
            for (int ni = 0; ni < 8; ni++) {
                int c = bn + n_w + ni * 8 + tq * 2;
                *(float2*)&Cout[(size_t)r0 * Ncols + c] =
                    make_float2(d[mi][ni][0] * s0, d[mi][ni][1] * s0);
                *(float2*)&Cout[(size_t)(r0 + 8) * Ncols + c] =
                    make_float2(d[mi][ni][2] * s1, d[mi][ni][3] * s1);
            }
        }
    } else {
        bool is_mu = (blockIdx.x == 0);
        float* F = is_mu ? muF : lvF;
        const float* bias = is_mu ? bmu : blv;
#pragma unroll
        for (int mi = 0; mi < 2; mi++) {
            int r0 = bm + m_w + mi * 16 + g4;
#pragma unroll
            for (int ni = 0; ni < 8; ni++) {
                int c = n_w + ni * 8 + tq * 2;
                float b0 = bias[c], b1 = bias[c + 1];
                float v00 = d[mi][ni][0] + b0, v01 = d[mi][ni][1] + b1;
                float v10 = d[mi][ni][2] + b0, v11 = d[mi][ni][3] + b1;
                *(float2*)&F[(size_t)r0 * LATD + c]       = make_float2(v00, v01);
                *(float2*)&F[(size_t)(r0 + 8) * LATD + c] = make_float2(v10, v11);
                if (is_mu) {
                    __nv_bfloat16 h0, h1, h2, h3, l0, l1, l2, l3;
                    split1(v00, h0, l0); split1(v01, h1, l1);
                    split1(v10, h2, l2); split1(v11, h3, l3);
                    uint32_t hv0 = ((uint32_t)__bfloat16_as_ushort(h1) << 16) | __bfloat16_as_ushort(h0);
                    uint32_t hv1 = ((uint32_t)__bfloat16_as_ushort(h3) << 16) | __bfloat16_as_ushort(h2);
                    uint32_t lv0 = ((uint32_t)__bfloat16_as_ushort(l1) << 16) | __bfloat16_as_ushort(l0);
                    uint32_t lv1 = ((uint32_t)__bfloat16_as_ushort(l3) << 16) | __bfloat16_as_ushort(l2);
                    *(uint32_t*)&ph[(size_t)r0 * LATD + c]       = hv0;
                    *(uint32_t*)&ph[(size_t)(r0 + 8) * LATD + c] = hv1;
                    *(uint32_t*)&pl[(size_t)r0 * LATD + c]       = lv0;
                    *(uint32_t*)&pl[(size_t)(r0 + 8) * LATD + c] = lv1;
                }
            }
        }
    }
}

// ---------------- adj = sigmoid(mu @ mu^T) via HMMA bf16-split ---------------
__device__ __forceinline__ void load_tile(const __nv_bfloat16* g, int rowblk, char* s) {
    const uint4* src = (const uint4*)(g + (size_t)rowblk * 128 * 128);
    int tid = threadIdx.x;
#pragma unroll
    for (int q = 0; q < 8; q++) {
        int idx = q * 256 + tid;
        int r = idx >> 4, c = idx & 15;
        *(uint4*)(s + r * TP2 + c * 16) = src[idx];
    }
}

__global__ void __launch_bounds__(256, 2)
k_adj_mma(const __nv_bfloat16* __restrict__ Ah, const __nv_bfloat16* __restrict__ Al,
          float* __restrict__ C)
{
    extern __shared__ __align__(16) char smem[];
    char* sA = smem;
    char* sB = smem + TILE_B;
    uint32_t sAu = smem_u32(sA), sBu = smem_u32(sB);

    int tid = threadIdx.x, wid = tid >> 5, lane = tid & 31;
    int m_w = (wid & 3) * 32, n_w = (wid >> 2) * 64;

    int t = blockIdx.x, bi = 0;
    while (t >= 64 - bi) { t -= 64 - bi; bi++; }
    int bj = bi + t;

    float d[2][8][4];
#pragma unroll
    for (int mi = 0; mi < 2; mi++)
#pragma unroll
        for (int ni = 0; ni < 8; ni++)
#pragma unroll
            for (int q = 0; q < 4; q++) d[mi][ni][q] = 0.f;

    load_tile(Ah, bi, sA);
    load_tile(Ah, bj, sB);
    __syncthreads();
    mma_pass(sAu, sBu, m_w, n_w, d, lane);
    __syncthreads();
    load_tile(Al, bj, sB);
    __syncthreads();
    mma_pass(sAu, sBu, m_w, n_w, d, lane);
    __syncthreads();
    load_tile(Al, bi, sA);
    load_tile(Ah, bj, sB);
    __syncthreads();
    mma_pass(sAu, sBu, m_w, n_w, d, lane);

#pragma unroll
    for (int mi = 0; mi < 2; mi++)
#pragma unroll
        for (int ni = 0; ni < 8; ni++)
#pragma unroll
            for (int q = 0; q < 4; q++)
                d[mi][ni][q] = 1.f / (1.f + __expf(-d[mi][ni][q]));

    int g4 = lane >> 2, tq = lane & 3;

#pragma unroll
    for (int mi = 0; mi < 2; mi++) {
        size_t r0 = (size_t)(bi * 128 + m_w + mi * 16 + g4);
#pragma unroll
        for (int ni = 0; ni < 8; ni++) {
            size_t cc = (size_t)(bj * 128 + n_w + ni * 8 + tq * 2);
            *(float2*)&C[r0 * NN + cc]       = make_float2(d[mi][ni][0], d[mi][ni][1]);
            *(float2*)&C[(r0 + 8) * NN + cc] = make_float2(d[mi][ni][2], d[mi][ni][3]);
        }
    }

    if (bi != bj) {
        __syncthreads();
        float* T = (float*)smem;
#pragma unroll
        for (int mi = 0; mi < 2; mi++) {
            int r = m_w + mi * 16 + g4;
#pragma unroll
            for (int ni = 0; ni < 8; ni++) {
                int c = n_w + ni * 8 + tq * 2;
                T[r * 129 + c]           = d[mi][ni][0];
                T[r * 129 + c + 1]       = d[mi][ni][1];
                T[(r + 8) * 129 + c]     = d[mi][ni][2];
                T[(r + 8) * 129 + c + 1] = d[mi][ni][3];
            }
        }
        __syncthreads();
#pragma unroll
        for (int q = 0; q < 64; q++) {
            int lin = q * 256 + tid;
            int cc = lin >> 7, rr = lin & 127;
            C[(size_t)(bj * 128 + cc) * NN + bi * 128 + rr] = T[rr * 129 + cc];
        }
    }
}

// ---------------- launch ----------------------------------------------------
extern "C" void kernel_launch(void* const* d_in, const int* in_sizes, int n_in,
                              void* d_out, int out_size)
{
    const float* x   = (const float*)d_in[0];
    const int*   ei  = (const int*)d_in[1];
    const float* W1  = (const float*)d_in[2];
    const float* b1  = (const float*)d_in[3];
    const float* W2  = (const float*)d_in[4];
    const float* b2  = (const float*)d_in[5];
    const float* Wmu = (const float*)d_in[6];
    const float* bmu = (const float*)d_in[7];
    const float* Wlv = (const float*)d_in[8];
    const float* blv = (const float*)d_in[9];

    float* out = (float*)d_out;
    float* mu  = out + (size_t)NN * NN;
    float* lv  = mu + (size_t)NN * LATD;

    float *p_hs1, *p_hs2, *p_dis;
    __nv_bfloat16 *p_xh, *p_xl, *p_z1h, *p_z1l, *p_z2h, *p_z2l, *p_muh, *p_mul;
    __nv_bfloat16 *p_w1h, *p_w1l, *p_w2h, *p_w2l, *p_whh, *p_whl;
    cudaGetSymbolAddress((void**)&p_hs1, g_hs1);
    cudaGetSymbolAddress((void**)&p_hs2, g_hs2);
    cudaGetSymbolAddress((void**)&p_dis, g_dis);
    cudaGetSymbolAddress((void**)&p_xh,  g_xh);
    cudaGetSymbolAddress((void**)&p_xl,  g_xl);
    cudaGetSymbolAddress((void**)&p_z1h, g_z1h);
    cudaGetSymbolAddress((void**)&p_z1l, g_z1l);
    cudaGetSymbolAddress((void**)&p_z2h, g_z2h);
    cudaGetSymbolAddress((void**)&p_z2l, g_z2l);
    cudaGetSymbolAddress((void**)&p_muh, g_muh);
    cudaGetSymbolAddress((void**)&p_mul, g_mul);
    cudaGetSymbolAddress((void**)&p_w1h, g_w1h);
    cudaGetSymbolAddress((void**)&p_w1l, g_w1l);
    cudaGetSymbolAddress((void**)&p_w2h, g_w2h);
    cudaGetSymbolAddress((void**)&p_w2l, g_w2l);
    cudaGetSymbolAddress((void**)&p_whh, g_whh);
    cudaGetSymbolAddress((void**)&p_whl, g_whl);

    cudaFuncSetAttribute(k_adj_mma, cudaFuncAttributeMaxDynamicSharedMemorySize, ADJ_SMEM);
    cudaFuncSetAttribute(k_gemm_tc, cudaFuncAttributeMaxDynamicSharedMemorySize, GEMM_SMEM);

    // graph preprocessing
    k_init  <<<8, 1024>>>();
    k_detect<<<32, 256>>>(ei);
    k_count <<<EE / 256, 256>>>(ei);
    k_scan  <<<1, 1024>>>();
    k_fill  <<<EE / 256, 256>>>(ei);

    // operand preparation (planes)
    k_split<<<(NN * DIN / 4) / 256, 256>>>(x, p_xh, p_xl);
    k_wsplit<<<(DIN * H1D) / 256, 256>>>(W1, p_w1h, p_w1l, DIN, H1D);
    k_wsplit<<<(H1D * LATD) / 256, 256>>>(W2, p_w2h, p_w2l, H1D, LATD);
    k_wsplit<<<(LATD * LATD) / 256, 256>>>(Wmu, p_whh, p_whl, LATD, LATD);
    k_wsplit<<<(LATD * LATD) / 256, 256>>>(Wlv, p_whh + LATD * LATD, p_whl + LATD * LATD, LATD, LATD);

    // layer 1: hs1 = dis * (x @ W1); agg -> z1 planes (relu)
    k_gemm_tc<<<dim3(H1D / 128, NN / 128), 256, GEMM_SMEM>>>(
        p_xh, p_xl, p_w1h, p_w1l, DIN, H1D, p_hs1, p_dis, 0,
        nullptr, nullptr, nullptr, nullptr, nullptr, nullptr);
    k_agg<<<NN, H1D>>>(p_hs1, b1, p_z1h, p_z1l, H1D, 1);

    // layer 2: hs2 = dis * (z1 @ W2); agg -> z2 planes
    k_gemm_tc<<<dim3(LATD / 128, NN / 128), 256, GEMM_SMEM>>>(
        p_z1h, p_z1l, p_w2h, p_w2l, H1D, LATD, p_hs2, p_dis, 0,
        nullptr, nullptr, nullptr, nullptr, nullptr, nullptr);
    k_agg<<<NN, LATD>>>(p_hs2, b2, p_z2h, p_z2l, LATD, 0);

    // fused heads: mu (+ planes) and logvar in one N=256 GEMM
    k_gemm_tc<<<dim3(2, NN / 128), 256, GEMM_SMEM>>>(
        p_z2h, p_z2l, p_whh, p_whl, LATD, 2 * LATD, nullptr, nullptr, 1,
        mu, lv, bmu, blv, p_muh, p_mul);

    // adj = sigmoid(mu @ mu^T)
    k_adj_mma<<<2080, 256, ADJ_SMEM>>>(p_muh, p_mul, out);
}

// round 9
// speedup vs baseline: 2.0042x; 1.0655x over previous
#include <cuda_runtime.h>
#include <cuda_bf16.h>
#include <math.h>
#include <stdint.h>

#define NN   8192
#define EE   262144
#define DIN  512
#define H1D  256
#define LATD 128

// ---------------- scratch (device globals; no allocation allowed) ----------
__device__ int   g_is64;
__device__ int   g_cnt[NN];
__device__ int   g_off[NN + 1];
__device__ int   g_cur[NN];
__device__ int   g_bsum[32];
__device__ int   g_boff[32];
__device__ int   g_csr[EE];
__device__ float g_dis[NN];
__device__ float g_hs1[NN * H1D];
__device__ float g_hs2[NN * LATD];
__device__ __nv_bfloat16 g_xh [NN * DIN],  g_xl [NN * DIN];
__device__ __nv_bfloat16 g_z1h[NN * H1D],  g_z1l[NN * H1D];
__device__ __nv_bfloat16 g_z2h[NN * LATD], g_z2l[NN * LATD];
__device__ __nv_bfloat16 g_muh[NN * LATD], g_mul[NN * LATD];
__device__ __nv_bfloat16 g_w1h[H1D * DIN],  g_w1l[H1D * DIN];
__device__ __nv_bfloat16 g_w2h[LATD * H1D], g_w2l[LATD * H1D];
__device__ __nv_bfloat16 g_whh[2 * LATD * LATD], g_whl[2 * LATD * LATD];

// ---------------- graph preprocessing --------------------------------------
__global__ void k_init() {
    int i = blockIdx.x * blockDim.x + threadIdx.x;
    if (i < NN) g_cnt[i] = 0;
    if (i == 0) g_is64 = 1;
}

__global__ void k_detect(const int* __restrict__ ei) {
    int i = blockIdx.x * blockDim.x + threadIdx.x;
    if (i < 8192) {
        if (ei[2 * i + 1] != 0) g_is64 = 0;
    }
}

__device__ __forceinline__ int edge_val(const int* ei, int idx) {
    return g_is64 ? ei[2 * idx] : ei[idx];
}

__global__ void k_count(const int* __restrict__ ei) {
    int e = blockIdx.x * blockDim.x + threadIdx.x;
    if (e >= EE) return;
    int c = edge_val(ei, EE + e);
    atomicAdd(&g_cnt[c], 1);
}

// hierarchical scan: A) 32 blocks local scan, B) scan 32 totals, C) fixup
__global__ void k_scan_a() {
    __shared__ int ws[8];
    int t = threadIdx.x, lane = t & 31, w = t >> 5;
    int i = blockIdx.x * 256 + t;
    int c = g_cnt[i];
    int v = c;
#pragma unroll
    for (int d = 1; d < 32; d <<= 1) {
        int u = __shfl_up_sync(0xffffffff, v, d);
        if (lane >= d) v += u;
    }
    if (lane == 31) ws[w] = v;
    __syncthreads();
    if (t < 8) {
        int x = ws[t];
#pragma unroll
        for (int d = 1; d < 8; d <<= 1) {
            int u = __shfl_up_sync(0xff, x, d);
            if (t >= d) x += u;
        }
        ws[t] = x;
    }
    __syncthreads();
    int excl = (w ? ws[w - 1] : 0) + v - c;
    g_off[i] = excl;
    g_dis[i] = rsqrtf((float)(c + 2));
    if (t == 255) g_bsum[blockIdx.x] = excl + c;
}

__global__ void k_scan_b() {
    int t = threadIdx.x;            // 32 threads
    int c = g_bsum[t];
    int v = c;
#pragma unroll
    for (int d = 1; d < 32; d <<= 1) {
        int u = __shfl_up_sync(0xffffffff, v, d);
        if (t >= d) v += u;
    }
    g_boff[t] = v - c;
    if (t == 31) g_off[NN] = v;
}

__global__ void k_scan_c() {
    int i = blockIdx.x * 256 + threadIdx.x;
    int o = g_off[i] + g_boff[blockIdx.x];
    g_off[i] = o;
    g_cur[i] = o;
}

__global__ void k_fill(const int* __restrict__ ei) {
    int e = blockIdx.x * blockDim.x + threadIdx.x;
    if (e >= EE) return;
    int r = edge_val(ei, e);
    int c = edge_val(ei, EE + e);
    int p = atomicAdd(&g_cur[c], 1);
    g_csr[p] = r;
}

// ---------------- split helpers ---------------------------------------------
__device__ __forceinline__ void split1(float v, __nv_bfloat16& h, __nv_bfloat16& l) {
    h = __float2bfloat16(v);
    l = __float2bfloat16(v - __bfloat162float(h));
}

__device__ __forceinline__ void split4(const float* src, int i,
                                       __nv_bfloat16* ph, __nv_bfloat16* pl) {
    float4 v = ((const float4*)src)[i];
    __nv_bfloat16 h0, h1, h2, h3, l0, l1, l2, l3;
    split1(v.x, h0, l0); split1(v.y, h1, l1); split1(v.z, h2, l2); split1(v.w, h3, l3);
    uint2 hv, lv;
    hv.x = ((uint32_t)__bfloat16_as_ushort(h1) << 16) | __bfloat16_as_ushort(h0);
    hv.y = ((uint32_t)__bfloat16_as_ushort(h3) << 16) | __bfloat16_as_ushort(h2);
    lv.x = ((uint32_t)__bfloat16_as_ushort(l1) << 16) | __bfloat16_as_ushort(l0);
    lv.y = ((uint32_t)__bfloat16_as_ushort(l3) << 16) | __bfloat16_as_ushort(l2);
    ((uint2*)ph)[i] = hv;
    ((uint2*)pl)[i] = lv;
}

__device__ __forceinline__ void wsplit1(const float* W, __nv_bfloat16* outh,
                                        __nv_bfloat16* outl, int Kdim, int Ndim, int idx) {
    int k = idx / Ndim, n = idx % Ndim;
    __nv_bfloat16 h, l;
    split1(W[idx], h, l);
    outh[(size_t)n * Kdim + k] = h;
    outl[(size_t)n * Kdim + k] = l;
}

// one kernel for all operand prep: x split (4096 blocks) + 4 weight transposes
__global__ void k_prep(const float* __restrict__ x,  const float* __restrict__ W1,
                       const float* __restrict__ W2, const float* __restrict__ Wmu,
                       const float* __restrict__ Wlv) {
    int b = blockIdx.x, t = threadIdx.x;
    if (b < 4096) {
        split4(x, b * 256 + t, g_xh, g_xl);
    } else if (b < 4608) {
        wsplit1(W1, g_w1h, g_w1l, DIN, H1D, (b - 4096) * 256 + t);
    } else if (b < 4736) {
        wsplit1(W2, g_w2h, g_w2l, H1D, LATD, (b - 4608) * 256 + t);
    } else if (b < 4800) {
        wsplit1(Wmu, g_whh, g_whl, LATD, LATD, (b - 4736) * 256 + t);
    } else {
        wsplit1(Wlv, g_whh + LATD * LATD, g_whl + LATD * LATD, LATD, LATD,
                (b - 4800) * 256 + t);
    }
}

// ---------------- neighborhood aggregation (MLP-4 gather) -------------------
__global__ void k_agg(const float* __restrict__ hs, const float* __restrict__ bias,
                      __nv_bfloat16* __restrict__ zh, __nv_bfloat16* __restrict__ zl,
                      int F, int relu)
{
    __shared__ int sj[256];
    int i = blockIdx.x;
    int f = threadIdx.x;
    float a0 = 2.f * hs[(size_t)i * F + f], a1 = 0.f, a2 = 0.f, a3 = 0.f;
    int s = g_off[i], e = g_off[i + 1];
    for (int base = s; base < e; base += blockDim.x) {
        int m = min((int)blockDim.x, e - base);
        __syncthreads();
        if (f < m) sj[f] = g_csr[base + f];
        __syncthreads();
        int p = 0;
        for (; p + 4 <= m; p += 4) {
            float v0 = hs[(size_t)sj[p + 0] * F + f];
            float v1 = hs[(size_t)sj[p + 1] * F + f];
            float v2 = hs[(size_t)sj[p + 2] * F + f];
            float v3 = hs[(size_t)sj[p + 3] * F + f];
            a0 += v0; a1 += v1; a2 += v2; a3 += v3;
        }
        for (; p < m; p++) a0 += hs[(size_t)sj[p] * F + f];
    }
    float v = g_dis[i] * ((a0 + a1) + (a2 + a3)) + bias[f];
    if (relu) v = fmaxf(v, 0.f);
    __nv_bfloat16 h, l;
    split1(v, h, l);
    zh[(size_t)i * F + f] = h;
    zl[(size_t)i * F + f] = l;
}

// ---------------- mma.sync helpers ------------------------------------------
__device__ __forceinline__ uint32_t smem_u32(const void* p) {
    uint32_t a;
    asm("{ .reg .u64 t; cvta.to.shared.u64 t, %1; cvt.u32.u64 %0, t; }" : "=r"(a) : "l"(p));
    return a;
}

__device__ __forceinline__ void ldsm_x4(uint32_t* r, uint32_t addr) {
    asm volatile("ldmatrix.sync.aligned.m8n8.x4.shared.b16 {%0,%1,%2,%3}, [%4];"
                 : "=r"(r[0]), "=r"(r[1]), "=r"(r[2]), "=r"(r[3]) : "r"(addr));
}

__device__ __forceinline__ void mma16816(float* d, const uint32_t* a, const uint32_t* b) {
    asm volatile("mma.sync.aligned.m16n8k16.row.col.f32.bf16.bf16.f32 "
                 "{%0,%1,%2,%3}, {%4,%5,%6,%7}, {%8,%9}, {%0,%1,%2,%3};"
                 : "+f"(d[0]), "+f"(d[1]), "+f"(d[2]), "+f"(d[3])
                 : "r"(a[0]), "r"(a[1]), "r"(a[2]), "r"(a[3]), "r"(b[0]), "r"(b[1]));
}

#define TP        136
#define TP2       (TP * 2)
#define TILE_B    (128 * TP2)             // 34816
#define ADJ_SMEM  (3 * TILE_B)            // 104448 (occ 2)
#define GEMM_SMEM (4 * TILE_B)            // 139264

__device__ __forceinline__ void mma_pass(uint32_t sA, uint32_t sB, int m_w, int n_w,
                                         float d[2][8][4], int lane) {
    uint32_t a_base = sA + ((m_w + (lane & 15)) * TP + (lane >> 4) * 8) * 2;
    int bmi = lane >> 3;
    uint32_t b_base = sB + ((n_w + ((bmi >> 1) * 8) + (lane & 7)) * TP + (bmi & 1) * 8) * 2;
#pragma unroll
    for (int kk = 0; kk < 8; kk++) {
        int k0 = kk * 16;
        uint32_t a[2][4];
        ldsm_x4(a[0], a_base + k0 * 2);
        ldsm_x4(a[1], a_base + (16 * TP + k0) * 2);
        uint32_t b[4][4];
#pragma unroll
        for (int np = 0; np < 4; np++)
            ldsm_x4(b[np], b_base + (np * 16 * TP + k0) * 2);
#pragma unroll
        for (int mi = 0; mi < 2; mi++)
#pragma unroll
            for (int np = 0; np < 4; np++) {
                mma16816(d[mi][np * 2 + 0], a[mi], &b[np][0]);
                mma16816(d[mi][np * 2 + 1], a[mi], &b[np][2]);
            }
    }
}

__device__ __forceinline__ void load_tile_k(const __nv_bfloat16* g, int row0, int K,
                                            int kc, char* s) {
    const __nv_bfloat16* base = g + (size_t)row0 * K + kc;
    int tid = threadIdx.x;
#pragma unroll
    for (int q = 0; q < 8; q++) {
        int idx = q * 256 + tid;
        int r = idx >> 4, c = idx & 15;
        *(uint4*)(s + r * TP2 + c * 16) = *(const uint4*)(base + (size_t)r * K + c * 8);
    }
}

// ---------------- unified bf16-split HMMA GEMM -------------------------------
__global__ void __launch_bounds__(256, 1)
k_gemm_tc(const __nv_bfloat16* __restrict__ Ah, const __nv_bfloat16* __restrict__ Al,
          const __nv_bfloat16* __restrict__ Bh, const __nv_bfloat16* __restrict__ Bl,
          int K, int Ncols,
          float* __restrict__ Cout, const float* __restrict__ scaleRow,
          int head,
          float* __restrict__ muF, float* __restrict__ lvF,
          const float* __restrict__ bmu, const float* __restrict__ blv,
          __nv_bfloat16* __restrict__ ph, __nv_bfloat16* __restrict__ pl)
{
    extern __shared__ __align__(16) char smem[];
    char* sAh = smem;
    char* sAl = smem + TILE_B;
    char* sBh = smem + 2 * TILE_B;
    char* sBl = smem + 3 * TILE_B;
    uint32_t uAh = smem_u32(sAh), uAl = smem_u32(sAl);
    uint32_t uBh = smem_u32(sBh), uBl = smem_u32(sBl);

    int tid = threadIdx.x, wid = tid >> 5, lane = tid & 31;
    int m_w = (wid & 3) * 32, n_w = (wid >> 2) * 64;
    int bm = blockIdx.y * 128, bn = blockIdx.x * 128;

    float d[2][8][4];
#pragma unroll
    for (int mi = 0; mi < 2; mi++)
#pragma unroll
        for (int ni = 0; ni < 8; ni++)
#pragma unroll
            for (int q = 0; q < 4; q++) d[mi][ni][q] = 0.f;

    for (int kc = 0; kc < K; kc += 128) {
        load_tile_k(Ah, bm, K, kc, sAh);
        load_tile_k(Al, bm, K, kc, sAl);
        load_tile_k(Bh, bn, K, kc, sBh);
        load_tile_k(Bl, bn, K, kc, sBl);
        __syncthreads();
        mma_pass(uAh, uBh, m_w, n_w, d, lane);
        mma_pass(uAh, uBl, m_w, n_w, d, lane);
        mma_pass(uAl, uBh, m_w, n_w, d, lane);
        __syncthreads();
    }

    int g4 = lane >> 2, tq = lane & 3;
    if (!head) {
#pragma unroll
        for (int mi = 0; mi < 2; mi++) {
            int r0 = bm + m_w + mi * 16 + g4;
            float s0 = scaleRow[r0], s1 = scaleRow[r0 + 8];
#pragma unroll
            for (int ni = 0; ni < 8; ni++) {
                int c = bn + n_w + ni * 8 + tq * 2;
                *(float2*)&Cout[(size_t)r0 * Ncols + c] =
                    make_float2(d[mi][ni][0] * s0, d[mi][ni][1] * s0);
                *(float2*)&Cout[(size_t)(r0 + 8) * Ncols + c] =
                    make_float2(d[mi][ni][2] * s1, d[mi][ni][3] * s1);
            }
        }
    } else {
        bool is_mu = (blockIdx.x == 0);
        float* F = is_mu ? muF : lvF;
        const float* bias = is_mu ? bmu : blv;
#pragma unroll
        for (int mi = 0; mi < 2; mi++) {
            int r0 = bm + m_w + mi * 16 + g4;
#pragma unroll
            for (int ni = 0; ni < 8; ni++) {
                int c = n_w + ni * 8 + tq * 2;
                float b0 = bias[c], b1 = bias[c + 1];
                float v00 = d[mi][ni][0] + b0, v01 = d[mi][ni][1] + b1;
                float v10 = d[mi][ni][2] + b0, v11 = d[mi][ni][3] + b1;
                *(float2*)&F[(size_t)r0 * LATD + c]       = make_float2(v00, v01);
                *(float2*)&F[(size_t)(r0 + 8) * LATD + c] = make_float2(v10, v11);
                if (is_mu) {
                    __nv_bfloat16 h0, h1, h2, h3, l0, l1, l2, l3;
                    split1(v00, h0, l0); split1(v01, h1, l1);
                    split1(v10, h2, l2); split1(v11, h3, l3);
                    uint32_t hv0 = ((uint32_t)__bfloat16_as_ushort(h1) << 16) | __bfloat16_as_ushort(h0);
                    uint32_t hv1 = ((uint32_t)__bfloat16_as_ushort(h3) << 16) | __bfloat16_as_ushort(h2);
                    uint32_t lv0 = ((uint32_t)__bfloat16_as_ushort(l1) << 16) | __bfloat16_as_ushort(l0);
                    uint32_t lv1 = ((uint32_t)__bfloat16_as_ushort(l3) << 16) | __bfloat16_as_ushort(l2);
                    *(uint32_t*)&ph[(size_t)r0 * LATD + c]       = hv0;
                    *(uint32_t*)&ph[(size_t)(r0 + 8) * LATD + c] = hv1;
                    *(uint32_t*)&pl[(size_t)r0 * LATD + c]       = lv0;
                    *(uint32_t*)&pl[(size_t)(r0 + 8) * LATD + c] = lv1;
                }
            }
        }
    }
}

// ---------------- adj = sigmoid(mu @ mu^T), 3-buffer HMMA --------------------
__device__ __forceinline__ void load_tile(const __nv_bfloat16* g, int rowblk, char* s) {
    const uint4* src = (const uint4*)(g + (size_t)rowblk * 128 * 128);
    int tid = threadIdx.x;
#pragma unroll
    for (int q = 0; q < 8; q++) {
        int idx = q * 256 + tid;
        int r = idx >> 4, c = idx & 15;
        *(uint4*)(s + r * TP2 + c * 16) = src[idx];
    }
}

__global__ void __launch_bounds__(256, 2)
k_adj_mma(const __nv_bfloat16* __restrict__ Ah, const __nv_bfloat16* __restrict__ Al,
          float* __restrict__ C)
{
    extern __shared__ __align__(16) char smem[];
    char* sA  = smem;                    // Ah[bi] then Al[bi]
    char* sBh = smem + TILE_B;           // Ah[bj]
    char* sBl = smem + 2 * TILE_B;       // Al[bj]
    uint32_t uA = smem_u32(sA), uBh = smem_u32(sBh), uBl = smem_u32(sBl);

    int tid = threadIdx.x, wid = tid >> 5, lane = tid & 31;
    int m_w = (wid & 3) * 32, n_w = (wid >> 2) * 64;

    int t = blockIdx.x, bi = 0;
    while (t >= 64 - bi) { t -= 64 - bi; bi++; }
    int bj = bi + t;

    float d[2][8][4];
#pragma unroll
    for (int mi = 0; mi < 2; mi++)
#pragma unroll
        for (int ni = 0; ni < 8; ni++)
#pragma unroll
            for (int q = 0; q < 4; q++) d[mi][ni][q] = 0.f;

    load_tile(Ah, bi, sA);
    load_tile(Ah, bj, sBh);
    load_tile(Al, bj, sBl);
    __syncthreads();
    mma_pass(uA, uBh, m_w, n_w, d, lane);     // Ah·Bh
    mma_pass(uA, uBl, m_w, n_w, d, lane);     // Ah·Bl
    __syncthreads();
    load_tile(Al, bi, sA);
    __syncthreads();
    mma_pass(uA, uBh, m_w, n_w, d, lane);     // Al·Bh

#pragma unroll
    for (int mi = 0; mi < 2; mi++)
#pragma unroll
        for (int ni = 0; ni < 8; ni++)
#pragma unroll
            for (int q = 0; q < 4; q++)
                d[mi][ni][q] = 1.f / (1.f + __expf(-d[mi][ni][q]));

    int g4 = lane >> 2, tq = lane & 3;

#pragma unroll
    for (int mi = 0; mi < 2; mi++) {
        size_t r0 = (size_t)(bi * 128 + m_w + mi * 16 + g4);
#pragma unroll
        for (int ni = 0; ni < 8; ni++) {
            size_t cc = (size_t)(bj * 128 + n_w + ni * 8 + tq * 2);
            *(float2*)&C[r0 * NN + cc]       = make_float2(d[mi][ni][0], d[mi][ni][1]);
            *(float2*)&C[(r0 + 8) * NN + cc] = make_float2(d[mi][ni][2], d[mi][ni][3]);
        }
    }

    if (bi != bj) {
        __syncthreads();
        float* T = (float*)smem;             // 128x129 fp32 = 66048 B, fits
#pragma unroll
        for (int mi = 0; mi < 2; mi++) {
            int r = m_w + mi * 16 + g4;
#pragma unroll
            for (int ni = 0; ni < 8; ni++) {
                int c = n_w + ni * 8 + tq * 2;
                T[r * 129 + c]           = d[mi][ni][0];
                T[r * 129 + c + 1]       = d[mi][ni][1];
                T[(r + 8) * 129 + c]     = d[mi][ni][2];
                T[(r + 8) * 129 + c + 1] = d[mi][ni][3];
            }
        }
        __syncthreads();
#pragma unroll
        for (int q = 0; q < 64; q++) {
            int lin = q * 256 + tid;
            int cc = lin >> 7, rr = lin & 127;
            C[(size_t)(bj * 128 + cc) * NN + bi * 128 + rr] = T[rr * 129 + cc];
        }
    }
}

// ---------------- launch ----------------------------------------------------
extern "C" void kernel_launch(void* const* d_in, const int* in_sizes, int n_in,
                              void* d_out, int out_size)
{
    const float* x   = (const float*)d_in[0];
    const int*   ei  = (const int*)d_in[1];
    const float* W1  = (const float*)d_in[2];
    const float* b1  = (const float*)d_in[3];
    const float* W2  = (const float*)d_in[4];
    const float* b2  = (const float*)d_in[5];
    const float* Wmu = (const float*)d_in[6];
    const float* bmu = (const float*)d_in[7];
    const float* Wlv = (const float*)d_in[8];
    const float* blv = (const float*)d_in[9];

    float* out = (float*)d_out;
    float* mu  = out + (size_t)NN * NN;
    float* lv  = mu + (size_t)NN * LATD;

    float *p_hs1, *p_hs2, *p_dis;
    __nv_bfloat16 *p_xh, *p_xl, *p_z1h, *p_z1l, *p_z2h, *p_z2l, *p_muh, *p_mul;
    __nv_bfloat16 *p_w1h, *p_w1l, *p_w2h, *p_w2l, *p_whh, *p_whl;
    cudaGetSymbolAddress((void**)&p_hs1, g_hs1);
    cudaGetSymbolAddress((void**)&p_hs2, g_hs2);
    cudaGetSymbolAddress((void**)&p_dis, g_dis);
    cudaGetSymbolAddress((void**)&p_xh,  g_xh);
    cudaGetSymbolAddress((void**)&p_xl,  g_xl);
    cudaGetSymbolAddress((void**)&p_z1h, g_z1h);
    cudaGetSymbolAddress((void**)&p_z1l, g_z1l);
    cudaGetSymbolAddress((void**)&p_z2h, g_z2h);
    cudaGetSymbolAddress((void**)&p_z2l, g_z2l);
    cudaGetSymbolAddress((void**)&p_muh, g_muh);
    cudaGetSymbolAddress((void**)&p_mul, g_mul);
    cudaGetSymbolAddress((void**)&p_w1h, g_w1h);
    cudaGetSymbolAddress((void**)&p_w1l, g_w1l);
    cudaGetSymbolAddress((void**)&p_w2h, g_w2h);
    cudaGetSymbolAddress((void**)&p_w2l, g_w2l);
    cudaGetSymbolAddress((void**)&p_whh, g_whh);
    cudaGetSymbolAddress((void**)&p_whl, g_whl);

    cudaFuncSetAttribute(k_adj_mma, cudaFuncAttributeMaxDynamicSharedMemorySize, ADJ_SMEM);
    cudaFuncSetAttribute(k_gemm_tc, cudaFuncAttributeMaxDynamicSharedMemorySize, GEMM_SMEM);

    // graph preprocessing
    k_init  <<<8, 1024>>>();
    k_detect<<<32, 256>>>(ei);
    k_count <<<EE / 256, 256>>>(ei);
    k_scan_a<<<32, 256>>>();
    k_scan_b<<<1, 32>>>();
    k_scan_c<<<32, 256>>>();
    k_fill  <<<EE / 256, 256>>>(ei);

    // operand preparation (x split + 4 weight transposes, one kernel)
    k_prep<<<4864, 256>>>(x, W1, W2, Wmu, Wlv);

    // layer 1: hs1 = dis * (x @ W1); agg -> z1 planes (relu)
    k_gemm_tc<<<dim3(H1D / 128, NN / 128), 256, GEMM_SMEM>>>(
        p_xh, p_xl, p_w1h, p_w1l, DIN, H1D, p_hs1, p_dis, 0,
        nullptr, nullptr, nullptr, nullptr, nullptr, nullptr);
    k_agg<<<NN, H1D>>>(p_hs1, b1, p_z1h, p_z1l, H1D, 1);

    // layer 2: hs2 = dis * (z1 @ W2); agg -> z2 planes
    k_gemm_tc<<<dim3(LATD / 128, NN / 128), 256, GEMM_SMEM>>>(
        p_z1h, p_z1l, p_w2h, p_w2l, H1D, LATD, p_hs2, p_dis, 0,
        nullptr, nullptr, nullptr, nullptr, nullptr, nullptr);
    k_agg<<<NN, LATD>>>(p_hs2, b2, p_z2h, p_z2l, LATD, 0);

    // fused heads: mu (+ planes) and logvar in one N=256 GEMM
    k_gemm_tc<<<dim3(2, NN / 128), 256, GEMM_SMEM>>>(
        p_z2h, p_z2l, p_whh, p_whl, LATD, 2 * LATD, nullptr, nullptr, 1,
        mu, lv, bmu, blv, p_muh, p_mul);

    // adj = sigmoid(mu @ mu^T)
    k_adj_mma<<<2080, 256, ADJ_SMEM>>>(p_muh, p_mul, out);
}

// round 11
// speedup vs baseline: 2.0915x; 1.0436x over previous
#include <cuda_runtime.h>
#include <cuda_bf16.h>
#include <math.h>
#include <stdint.h>

#define NN   8192
#define EE   262144
#define DIN  512
#define H1D  256
#define LATD 128

// ---------------- scratch (device globals; no allocation allowed) ----------
__device__ int   g_is64;
__device__ int   g_cnt[NN];
__device__ int   g_off[NN + 1];
__device__ int   g_cur[NN];
__device__ int   g_bsum[32];
__device__ int   g_boff[32];
__device__ int   g_csr[EE];
__device__ float g_dis[NN];
__device__ float g_hs1[NN * H1D];
__device__ float g_hs2[NN * LATD];
__device__ __nv_bfloat16 g_xh [NN * DIN],  g_xl [NN * DIN];
__device__ __nv_bfloat16 g_z1h[NN * H1D],  g_z1l[NN * H1D];
__device__ __nv_bfloat16 g_z2h[NN * LATD], g_z2l[NN * LATD];
__device__ __nv_bfloat16 g_muh[NN * LATD], g_mul[NN * LATD];
__device__ __nv_bfloat16 g_w1h[H1D * DIN],  g_w1l[H1D * DIN];
__device__ __nv_bfloat16 g_w2h[LATD * H1D], g_w2l[LATD * H1D];
__device__ __nv_bfloat16 g_whh[2 * LATD * LATD], g_whl[2 * LATD * LATD];

// ---------------- split helpers ---------------------------------------------
__device__ __forceinline__ void split1(float v, __nv_bfloat16& h, __nv_bfloat16& l) {
    h = __float2bfloat16(v);
    l = __float2bfloat16(v - __bfloat162float(h));
}

__device__ __forceinline__ void split4(const float* src, int i,
                                       __nv_bfloat16* ph, __nv_bfloat16* pl) {
    float4 v = ((const float4*)src)[i];
    __nv_bfloat16 h0, h1, h2, h3, l0, l1, l2, l3;
    split1(v.x, h0, l0); split1(v.y, h1, l1); split1(v.z, h2, l2); split1(v.w, h3, l3);
    uint2 hv, lv;
    hv.x = ((uint32_t)__bfloat16_as_ushort(h1) << 16) | __bfloat16_as_ushort(h0);
    hv.y = ((uint32_t)__bfloat16_as_ushort(h3) << 16) | __bfloat16_as_ushort(h2);
    lv.x = ((uint32_t)__bfloat16_as_ushort(l1) << 16) | __bfloat16_as_ushort(l0);
    lv.y = ((uint32_t)__bfloat16_as_ushort(l3) << 16) | __bfloat16_as_ushort(l2);
    ((uint2*)ph)[i] = hv;
    ((uint2*)pl)[i] = lv;
}

__device__ __forceinline__ void wsplit1(const float* W, __nv_bfloat16* outh,
                                        __nv_bfloat16* outl, int Kdim, int Ndim, int idx) {
    int k = idx / Ndim, n = idx % Ndim;
    __nv_bfloat16 h, l;
    split1(W[idx], h, l);
    outh[(size_t)n * Kdim + k] = h;
    outl[(size_t)n * Kdim + k] = l;
}

// ---------------- launch 1: zero counts, set is64 ---------------------------
__global__ void k_init() {
    int i = blockIdx.x * blockDim.x + threadIdx.x;
    if (i < NN) g_cnt[i] = 0;
    if (i == 0) g_is64 = 1;
}

// ---------------- launch 2: edge-width detect + all operand prep ------------
__global__ void k_detprep(const int* __restrict__ ei, const float* __restrict__ x,
                          const float* __restrict__ W1, const float* __restrict__ W2,
                          const float* __restrict__ Wmu, const float* __restrict__ Wlv) {
    int b = blockIdx.x, t = threadIdx.x;
    if (b < 32) {
        int i = b * 256 + t;
        if (ei[2 * i + 1] != 0) g_is64 = 0;
        return;
    }
    b -= 32;
    if (b < 4096) {
        split4(x, b * 256 + t, g_xh, g_xl);
    } else if (b < 4608) {
        wsplit1(W1, g_w1h, g_w1l, DIN, H1D, (b - 4096) * 256 + t);
    } else if (b < 4736) {
        wsplit1(W2, g_w2h, g_w2l, H1D, LATD, (b - 4608) * 256 + t);
    } else if (b < 4800) {
        wsplit1(Wmu, g_whh, g_whl, LATD, LATD, (b - 4736) * 256 + t);
    } else {
        wsplit1(Wlv, g_whh + LATD * LATD, g_whl + LATD * LATD, LATD, LATD,
                (b - 4800) * 256 + t);
    }
}

__device__ __forceinline__ int edge_val(const int* ei, int idx) {
    return g_is64 ? ei[2 * idx] : ei[idx];
}

// ---------------- launch 3: degree count ------------------------------------
__global__ void k_count(const int* __restrict__ ei) {
    int e = blockIdx.x * blockDim.x + threadIdx.x;
    if (e >= EE) return;
    int c = edge_val(ei, EE + e);
    atomicAdd(&g_cnt[c], 1);
}

// ---------------- hierarchical scan (launches 5-7) --------------------------
__global__ void k_scan_a() {
    __shared__ int ws[8];
    int t = threadIdx.x, lane = t & 31, w = t >> 5;
    int i = blockIdx.x * 256 + t;
    int c = g_cnt[i];
    int v = c;
#pragma unroll
    for (int d = 1; d < 32; d <<= 1) {
        int u = __shfl_up_sync(0xffffffff, v, d);
        if (lane >= d) v += u;
    }
    if (lane == 31) ws[w] = v;
    __syncthreads();
    if (t < 8) {
        int x = ws[t];
#pragma unroll
        for (int d = 1; d < 8; d <<= 1) {
            int u = __shfl_up_sync(0xff, x, d);
            if (t >= d) x += u;
        }
        ws[t] = x;
    }
    __syncthreads();
    int excl = (w ? ws[w - 1] : 0) + v - c;
    g_off[i] = excl;
    g_dis[i] = rsqrtf((float)(c + 2));
    if (t == 255) g_bsum[blockIdx.x] = excl + c;
}

__global__ void k_scan_b() {
    int t = threadIdx.x;
    int c = g_bsum[t];
    int v = c;
#pragma unroll
    for (int d = 1; d < 32; d <<= 1) {
        int u = __shfl_up_sync(0xffffffff, v, d);
        if (t >= d) v += u;
    }
    g_boff[t] = v - c;
    if (t == 31) g_off[NN] = v;
}

__global__ void k_scan_c() {
    int i = blockIdx.x * 256 + threadIdx.x;
    int o = g_off[i] + g_boff[blockIdx.x];
    g_off[i] = o;
    g_cur[i] = o;
}

__global__ void k_fill(const int* __restrict__ ei) {
    int e = blockIdx.x * blockDim.x + threadIdx.x;
    if (e >= EE) return;
    int r = edge_val(ei, e);
    int c = edge_val(ei, EE + e);
    int p = atomicAdd(&g_cur[c], 1);
    g_csr[p] = r;
}

// ---------------- neighborhood aggregation (dis applied in gather) ----------
// out_i = maybe_relu( dis_i * ( sum_j dis_j*hs_j + 2*dis_i*hs_i ) + bias )
__global__ void k_agg(const float* __restrict__ hs, const float* __restrict__ bias,
                      __nv_bfloat16* __restrict__ zh, __nv_bfloat16* __restrict__ zl,
                      int F, int relu)
{
    __shared__ int   sj[256];
    __shared__ float sd[256];
    int i = blockIdx.x;
    int f = threadIdx.x;
    float di = g_dis[i];
    float a0 = 2.f * di * hs[(size_t)i * F + f], a1 = 0.f, a2 = 0.f, a3 = 0.f;
    int s = g_off[i], e = g_off[i + 1];
    for (int base = s; base < e; base += blockDim.x) {
        int m = min((int)blockDim.x, e - base);
        __syncthreads();
        if (f < m) {
            int j = g_csr[base + f];
            sj[f] = j;
            sd[f] = g_dis[j];
        }
        __syncthreads();
        int p = 0;
        for (; p + 4 <= m; p += 4) {
            float v0 = hs[(size_t)sj[p + 0] * F + f];
            float v1 = hs[(size_t)sj[p + 1] * F + f];
            float v2 = hs[(size_t)sj[p + 2] * F + f];
            float v3 = hs[(size_t)sj[p + 3] * F + f];
            a0 = fmaf(sd[p + 0], v0, a0);
            a1 = fmaf(sd[p + 1], v1, a1);
            a2 = fmaf(sd[p + 2], v2, a2);
            a3 = fmaf(sd[p + 3], v3, a3);
        }
        for (; p < m; p++) a0 = fmaf(sd[p], hs[(size_t)sj[p] * F + f], a0);
    }
    float v = di * ((a0 + a1) + (a2 + a3)) + bias[f];
    if (relu) v = fmaxf(v, 0.f);
    __nv_bfloat16 h, l;
    split1(v, h, l);
    zh[(size_t)i * F + f] = h;
    zl[(size_t)i * F + f] = l;
}

// ---------------- mma.sync helpers ------------------------------------------
__device__ __forceinline__ uint32_t smem_u32(const void* p) {
    uint32_t a;
    asm("{ .reg .u64 t; cvta.to.shared.u64 t, %1; cvt.u32.u64 %0, t; }" : "=r"(a) : "l"(p));
    return a;
}

__device__ __forceinline__ void ldsm_x4(uint32_t* r, uint32_t addr) {
    asm volatile("ldmatrix.sync.aligned.m8n8.x4.shared.b16 {%0,%1,%2,%3}, [%4];"
                 : "=r"(r[0]), "=r"(r[1]), "=r"(r[2]), "=r"(r[3]) : "r"(addr));
}

__device__ __forceinline__ void mma16816(float* d, const uint32_t* a, const uint32_t* b) {
    asm volatile("mma.sync.aligned.m16n8k16.row.col.f32.bf16.bf16.f32 "
                 "{%0,%1,%2,%3}, {%4,%5,%6,%7}, {%8,%9}, {%0,%1,%2,%3};"
                 : "+f"(d[0]), "+f"(d[1]), "+f"(d[2]), "+f"(d[3])
                 : "r"(a[0]), "r"(a[1]), "r"(a[2]), "r"(a[3]), "r"(b[0]), "r"(b[1]));
}

__device__ __forceinline__ void cpa16(uint32_t saddr, const void* g) {
    asm volatile("cp.async.cg.shared.global [%0], [%1], 16;"
                 :: "r"(saddr), "l"(g) : "memory");
}
#define CP_COMMIT() asm volatile("cp.async.commit_group;" ::: "memory")
#define CP_WAIT0()  asm volatile("cp.async.wait_group 0;" ::: "memory")

#define TP        136
#define TP2       (TP * 2)
#define TILE_B    (128 * TP2)             // 34816
#define ADJ_SMEM  (3 * TILE_B)            // 104448 (occ 2)
#define GEMM_SMEM (4 * TILE_B)            // 139264

__device__ __forceinline__ void mma_pass(uint32_t sA, uint32_t sB, int m_w, int n_w,
                                         float d[2][8][4], int lane) {
    uint32_t a_base = sA + ((m_w + (lane & 15)) * TP + (lane >> 4) * 8) * 2;
    int bmi = lane >> 3;
    uint32_t b_base = sB + ((n_w + ((bmi >> 1) * 8) + (lane & 7)) * TP + (bmi & 1) * 8) * 2;
#pragma unroll
    for (int kk = 0; kk < 8; kk++) {
        int k0 = kk * 16;
        uint32_t a[2][4];
        ldsm_x4(a[0], a_base + k0 * 2);
        ldsm_x4(a[1], a_base + (16 * TP + k0) * 2);
        uint32_t b[4][4];
#pragma unroll
        for (int np = 0; np < 4; np++)
            ldsm_x4(b[np], b_base + (np * 16 * TP + k0) * 2);
#pragma unroll
        for (int mi = 0; mi < 2; mi++)
#pragma unroll
            for (int np = 0; np < 4; np++) {
                mma16816(d[mi][np * 2 + 0], a[mi], &b[np][0]);
                mma16816(d[mi][np * 2 + 1], a[mi], &b[np][2]);
            }
    }
}

__device__ __forceinline__ void load_tile_k(const __nv_bfloat16* g, int row0, int K,
                                            int kc, char* s) {
    const __nv_bfloat16* base = g + (size_t)row0 * K + kc;
    int tid = threadIdx.x;
#pragma unroll
    for (int q = 0; q < 8; q++) {
        int idx = q * 256 + tid;
        int r = idx >> 4, c = idx & 15;
        *(uint4*)(s + r * TP2 + c * 16) = *(const uint4*)(base + (size_t)r * K + c * 8);
    }
}

// cp.async 128x128 bf16 tile load (contiguous 128-row block)
__device__ __forceinline__ void load_tile_cpa(const __nv_bfloat16* g, int rowblk,
                                              uint32_t s_u32) {
    const uint4* src = (const uint4*)(g + (size_t)rowblk * 128 * 128);
    int tid = threadIdx.x;
#pragma unroll
    for (int q = 0; q < 8; q++) {
        int idx = q * 256 + tid;
        int r = idx >> 4, c = idx & 15;
        cpa16(s_u32 + r * TP2 + c * 16, src + idx);
    }
}

// ---------------- unified bf16-split HMMA GEMM -------------------------------
// layer mode (head==0): Cout = A@B^T (plain)
// head mode  (head==1): blockIdx.x==0 -> mu (+bf16 planes), ==1 -> logvar
__global__ void __launch_bounds__(256, 1)
k_gemm_tc(const __nv_bfloat16* __restrict__ Ah, const __nv_bfloat16* __restrict__ Al,
          const __nv_bfloat16* __restrict__ Bh, const __nv_bfloat16* __restrict__ Bl,
          int K, int Ncols,
          float* __restrict__ Cout,
          int head,
          float* __restrict__ muF, float* __restrict__ lvF,
          const float* __restrict__ bmu, const float* __restrict__ blv,
          __nv_bfloat16* __restrict__ ph, __nv_bfloat16* __restrict__ pl)
{
    extern __shared__ __align__(16) char smem[];
    char* sAh = smem;
    char* sAl = smem + TILE_B;
    char* sBh = smem + 2 * TILE_B;
    char* sBl = smem + 3 * TILE_B;
    uint32_t uAh = smem_u32(sAh), uAl = smem_u32(sAl);
    uint32_t uBh = smem_u32(sBh), uBl = smem_u32(sBl);

    int tid = threadIdx.x, wid = tid >> 5, lane = tid & 31;
    int m_w = (wid & 3) * 32, n_w = (wid >> 2) * 64;
    int bm = blockIdx.y * 128, bn = blockIdx.x * 128;

    float d[2][8][4];
#pragma unroll
    for (int mi = 0; mi < 2; mi++)
#pragma unroll
        for (int ni = 0; ni < 8; ni++)
#pragma unroll
            for (int q = 0; q < 4; q++) d[mi][ni][q] = 0.f;

    for (int kc = 0; kc < K; kc += 128) {
        load_tile_k(Ah, bm, K, kc, sAh);
        load_tile_k(Al, bm, K, kc, sAl);
        load_tile_k(Bh, bn, K, kc, sBh);
        load_tile_k(Bl, bn, K, kc, sBl);
        __syncthreads();
        mma_pass(uAh, uBh, m_w, n_w, d, lane);
        mma_pass(uAh, uBl, m_w, n_w, d, lane);
        mma_pass(uAl, uBh, m_w, n_w, d, lane);
        __syncthreads();
    }

    int g4 = lane >> 2, tq = lane & 3;
    if (!head) {
#pragma unroll
        for (int mi = 0; mi < 2; mi++) {
            int r0 = bm + m_w + mi * 16 + g4;
#pragma unroll
            for (int ni = 0; ni < 8; ni++) {
                int c = bn + n_w + ni * 8 + tq * 2;
                *(float2*)&Cout[(size_t)r0 * Ncols + c] =
                    make_float2(d[mi][ni][0], d[mi][ni][1]);
                *(float2*)&Cout[(size_t)(r0 + 8) * Ncols + c] =
                    make_float2(d[mi][ni][2], d[mi][ni][3]);
            }
        }
    } else {
        bool is_mu = (blockIdx.x == 0);
        float* F = is_mu ? muF : lvF;
        const float* bias = is_mu ? bmu : blv;
#pragma unroll
        for (int mi = 0; mi < 2; mi++) {
            int r0 = bm + m_w + mi * 16 + g4;
#pragma unroll
            for (int ni = 0; ni < 8; ni++) {
                int c = n_w + ni * 8 + tq * 2;
                float b0 = bias[c], b1 = bias[c + 1];
                float v00 = d[mi][ni][0] + b0, v01 = d[mi][ni][1] + b1;
                float v10 = d[mi][ni][2] + b0, v11 = d[mi][ni][3] + b1;
                *(float2*)&F[(size_t)r0 * LATD + c]       = make_float2(v00, v01);
                *(float2*)&F[(size_t)(r0 + 8) * LATD + c] = make_float2(v10, v11);
                if (is_mu) {
                    __nv_bfloat16 h0, h1, h2, h3, l0, l1, l2, l3;
                    split1(v00, h0, l0); split1(v01, h1, l1);
                    split1(v10, h2, l2); split1(v11, h3, l3);
                    uint32_t hv0 = ((uint32_t)__bfloat16_as_ushort(h1) << 16) | __bfloat16_as_ushort(h0);
                    uint32_t hv1 = ((uint32_t)__bfloat16_as_ushort(h3) << 16) | __bfloat16_as_ushort(h2);
                    uint32_t lv0 = ((uint32_t)__bfloat16_as_ushort(l1) << 16) | __bfloat16_as_ushort(l0);
                    uint32_t lv1 = ((uint32_t)__bfloat16_as_ushort(l3) << 16) | __bfloat16_as_ushort(l2);
                    *(uint32_t*)&ph[(size_t)r0 * LATD + c]       = hv0;
                    *(uint32_t*)&ph[(size_t)(r0 + 8) * LATD + c] = hv1;
                    *(uint32_t*)&pl[(size_t)r0 * LATD + c]       = lv0;
                    *(uint32_t*)&pl[(size_t)(r0 + 8) * LATD + c] = lv1;
                }
            }
        }
    }
}

// ---------------- adj = sigmoid(mu @ mu^T), cp.async-overlapped --------------
// pass order: Ah·Bl, Ah·Bh (overlaps Al[bi] cp.async into dead sBl), Al·Bh
__global__ void __launch_bounds__(256, 2)
k_adj_mma(const __nv_bfloat16* __restrict__ Ah, const __nv_bfloat16* __restrict__ Al,
          float* __restrict__ C)
{
    extern __shared__ __align__(16) char smem[];
    char* sA  = smem;                    // Ah[bi]
    char* sBh = smem + TILE_B;           // Ah[bj]
    char* sBl = smem + 2 * TILE_B;       // Al[bj] then Al[bi]
    uint32_t uA = smem_u32(sA), uBh = smem_u32(sBh), uBl = smem_u32(sBl);

    int tid = threadIdx.x, wid = tid >> 5, lane = tid & 31;
    int m_w = (wid & 3) * 32, n_w = (wid >> 2) * 64;

    int t = blockIdx.x, bi = 0;
    while (t >= 64 - bi) { t -= 64 - bi; bi++; }
    int bj = bi + t;

    float d[2][8][4];
#pragma unroll
    for (int mi = 0; mi < 2; mi++)
#pragma unroll
        for (int ni = 0; ni < 8; ni++)
#pragma unroll
            for (int q = 0; q < 4; q++) d[mi][ni][q] = 0.f;

    load_tile_cpa(Ah, bi, uA);
    load_tile_cpa(Ah, bj, uBh);
    load_tile_cpa(Al, bj, uBl);
    CP_COMMIT();
    CP_WAIT0();
    __syncthreads();

    mma_pass(uA, uBl, m_w, n_w, d, lane);     // Ah_i · Al_j^T
    __syncthreads();                           // sBl now dead for reads
    load_tile_cpa(Al, bi, uBl);                // async reload, overlaps next pass
    CP_COMMIT();
    mma_pass(uA, uBh, m_w, n_w, d, lane);     // Ah_i · Ah_j^T
    CP_WAIT0();
    __syncthreads();
    mma_pass(uBl, uBh, m_w, n_w, d, lane);    // Al_i · Ah_j^T

#pragma unroll
    for (int mi = 0; mi < 2; mi++)
#pragma unroll
        for (int ni = 0; ni < 8; ni++)
#pragma unroll
            for (int q = 0; q < 4; q++)
                d[mi][ni][q] = 1.f / (1.f + __expf(-d[mi][ni][q]));

    int g4 = lane >> 2, tq = lane & 3;

#pragma unroll
    for (int mi = 0; mi < 2; mi++) {
        size_t r0 = (size_t)(bi * 128 + m_w + mi * 16 + g4);
#pragma unroll
        for (int ni = 0; ni < 8; ni++) {
            size_t cc = (size_t)(bj * 128 + n_w + ni * 8 + tq * 2);
            *(float2*)&C[r0 * NN + cc]       = make_float2(d[mi][ni][0], d[mi][ni][1]);
            *(float2*)&C[(r0 + 8) * NN + cc] = make_float2(d[mi][ni][2], d[mi][ni][3]);
        }
    }

    if (bi != bj) {
        __syncthreads();
        float* T = (float*)smem;             // 128x129 fp32 = 66048 B, fits
#pragma unroll
        for (int mi = 0; mi < 2; mi++) {
            int r = m_w + mi * 16 + g4;
#pragma unroll
            for (int ni = 0; ni < 8; ni++) {
                int c = n_w + ni * 8 + tq * 2;
                T[r * 129 + c]           = d[mi][ni][0];
                T[r * 129 + c + 1]       = d[mi][ni][1];
                T[(r + 8) * 129 + c]     = d[mi][ni][2];
                T[(r + 8) * 129 + c + 1] = d[mi][ni][3];
            }
        }
        __syncthreads();
#pragma unroll
        for (int q = 0; q < 64; q++) {
            int lin = q * 256 + tid;
            int cc = lin >> 7, rr = lin & 127;
            C[(size_t)(bj * 128 + cc) * NN + bi * 128 + rr] = T[rr * 129 + cc];
        }
    }
}

// ---------------- launch ----------------------------------------------------
extern "C" void kernel_launch(void* const* d_in, const int* in_sizes, int n_in,
                              void* d_out, int out_size)
{
    const float* x   = (const float*)d_in[0];
    const int*   ei  = (const int*)d_in[1];
    const float* W1  = (const float*)d_in[2];
    const float* b1  = (const float*)d_in[3];
    const float* W2  = (const float*)d_in[4];
    const float* b2  = (const float*)d_in[5];
    const float* Wmu = (const float*)d_in[6];
    const float* bmu = (const float*)d_in[7];
    const float* Wlv = (const float*)d_in[8];
    const float* blv = (const float*)d_in[9];

    float* out = (float*)d_out;
    float* mu  = out + (size_t)NN * NN;
    float* lv  = mu + (size_t)NN * LATD;

    float *p_hs1, *p_hs2;
    __nv_bfloat16 *p_xh, *p_xl, *p_z1h, *p_z1l, *p_z2h, *p_z2l, *p_muh, *p_mul;
    __nv_bfloat16 *p_w1h, *p_w1l, *p_w2h, *p_w2l, *p_whh, *p_whl;
    cudaGetSymbolAddress((void**)&p_hs1, g_hs1);
    cudaGetSymbolAddress((void**)&p_hs2, g_hs2);
    cudaGetSymbolAddress((void**)&p_xh,  g_xh);
    cudaGetSymbolAddress((void**)&p_xl,  g_xl);
    cudaGetSymbolAddress((void**)&p_z1h, g_z1h);
    cudaGetSymbolAddress((void**)&p_z1l, g_z1l);
    cudaGetSymbolAddress((void**)&p_z2h, g_z2h);
    cudaGetSymbolAddress((void**)&p_z2l, g_z2l);
    cudaGetSymbolAddress((void**)&p_muh, g_muh);
    cudaGetSymbolAddress((void**)&p_mul, g_mul);
    cudaGetSymbolAddress((void**)&p_w1h, g_w1h);
    cudaGetSymbolAddress((void**)&p_w1l, g_w1l);
    cudaGetSymbolAddress((void**)&p_w2h, g_w2h);
    cudaGetSymbolAddress((void**)&p_w2l, g_w2l);
    cudaGetSymbolAddress((void**)&p_whh, g_whh);
    cudaGetSymbolAddress((void**)&p_whl, g_whl);

    cudaFuncSetAttribute(k_adj_mma, cudaFuncAttributeMaxDynamicSharedMemorySize, ADJ_SMEM);
    cudaFuncSetAttribute(k_gemm_tc, cudaFuncAttributeMaxDynamicSharedMemorySize, GEMM_SMEM);

    // 1-3: init, detect+prep, count  (GEMM1 lands at launch #4 for ncu)
    k_init   <<<8, 1024>>>();
    k_detprep<<<4896, 256>>>(ei, x, W1, W2, Wmu, Wlv);
    k_count  <<<EE / 256, 256>>>(ei);

    // 4: layer-1 GEMM (plain x@W1; dis now applied inside agg)
    k_gemm_tc<<<dim3(H1D / 128, NN / 128), 256, GEMM_SMEM>>>(
        p_xh, p_xl, p_w1h, p_w1l, DIN, H1D, p_hs1, 0,
        nullptr, nullptr, nullptr, nullptr, nullptr, nullptr);

    // 5-8: scan + CSR fill
    k_scan_a<<<32, 256>>>();
    k_scan_b<<<1, 32>>>();
    k_scan_c<<<32, 256>>>();
    k_fill  <<<EE / 256, 256>>>(ei);

    // 9: agg1 -> z1 planes (relu)
    k_agg<<<NN, H1D>>>(p_hs1, b1, p_z1h, p_z1l, H1D, 1);

    // 10-11: layer-2 GEMM + agg2
    k_gemm_tc<<<dim3(LATD / 128, NN / 128), 256, GEMM_SMEM>>>(
        p_z1h, p_z1l, p_w2h, p_w2l, H1D, LATD, p_hs2, 0,
        nullptr, nullptr, nullptr, nullptr, nullptr, nullptr);
    k_agg<<<NN, LATD>>>(p_hs2, b2, p_z2h, p_z2l, LATD, 0);

    // 12: fused heads
    k_gemm_tc<<<dim3(2, NN / 128), 256, GEMM_SMEM>>>(
        p_z2h, p_z2l, p_whh, p_whl, LATD, 2 * LATD, nullptr, 1,
        mu, lv, bmu, blv, p_muh, p_mul);

    // 13: adj = sigmoid(mu @ mu^T)
    k_adj_mma<<<2080, 256, ADJ_SMEM>>>(p_muh, p_mul, out);
}

// round 12
// speedup vs baseline: 2.1522x; 1.0290x over previous
#include <cuda_runtime.h>
#include <cuda_bf16.h>
#include <math.h>
#include <stdint.h>

#define NN   8192
#define EE   262144
#define DIN  512
#define H1D  256
#define LATD 128

// ---------------- scratch (device globals; no allocation allowed) ----------
__device__ int   g_is64;
__device__ int   g_cnt[NN];
__device__ int   g_off[NN + 1];
__device__ int   g_cur[NN];
__device__ int   g_bsum[32];
__device__ int   g_boff[32];
__device__ int   g_csr[EE];
__device__ float g_dis[NN];
__device__ float g_hs1[NN * H1D];
__device__ float g_hs2[NN * LATD];
__device__ __nv_bfloat16 g_xh [NN * DIN],  g_xl [NN * DIN];
__device__ __nv_bfloat16 g_z1h[NN * H1D],  g_z1l[NN * H1D];
__device__ __nv_bfloat16 g_z2h[NN * LATD], g_z2l[NN * LATD];
__device__ __nv_bfloat16 g_muh[NN * LATD], g_mul[NN * LATD];
__device__ __nv_bfloat16 g_w1h[H1D * DIN],  g_w1l[H1D * DIN];
__device__ __nv_bfloat16 g_w2h[LATD * H1D], g_w2l[LATD * H1D];
__device__ __nv_bfloat16 g_whh[2 * LATD * LATD], g_whl[2 * LATD * LATD];

// ---------------- split helpers ---------------------------------------------
__device__ __forceinline__ void split1(float v, __nv_bfloat16& h, __nv_bfloat16& l) {
    h = __float2bfloat16(v);
    l = __float2bfloat16(v - __bfloat162float(h));
}

__device__ __forceinline__ void split4(const float* src, int i,
                                       __nv_bfloat16* ph, __nv_bfloat16* pl) {
    float4 v = ((const float4*)src)[i];
    __nv_bfloat16 h0, h1, h2, h3, l0, l1, l2, l3;
    split1(v.x, h0, l0); split1(v.y, h1, l1); split1(v.z, h2, l2); split1(v.w, h3, l3);
    uint2 hv, lv;
    hv.x = ((uint32_t)__bfloat16_as_ushort(h1) << 16) | __bfloat16_as_ushort(h0);
    hv.y = ((uint32_t)__bfloat16_as_ushort(h3) << 16) | __bfloat16_as_ushort(h2);
    lv.x = ((uint32_t)__bfloat16_as_ushort(l1) << 16) | __bfloat16_as_ushort(l0);
    lv.y = ((uint32_t)__bfloat16_as_ushort(l3) << 16) | __bfloat16_as_ushort(l2);
    ((uint2*)ph)[i] = hv;
    ((uint2*)pl)[i] = lv;
}

__device__ __forceinline__ void wsplit1(const float* W, __nv_bfloat16* outh,
                                        __nv_bfloat16* outl, int Kdim, int Ndim, int idx) {
    int k = idx / Ndim, n = idx % Ndim;
    __nv_bfloat16 h, l;
    split1(W[idx], h, l);
    outh[(size_t)n * Kdim + k] = h;
    outl[(size_t)n * Kdim + k] = l;
}

// ---------------- launch 1: zero counts, set is64 ---------------------------
__global__ void k_init() {
    int i = blockIdx.x * blockDim.x + threadIdx.x;
    if (i < NN) g_cnt[i] = 0;
    if (i == 0) g_is64 = 1;
}

// ---------------- launch 2: edge-width detect + all operand prep ------------
__global__ void k_detprep(const int* __restrict__ ei, const float* __restrict__ x,
                          const float* __restrict__ W1, const float* __restrict__ W2,
                          const float* __restrict__ Wmu, const float* __restrict__ Wlv) {
    int b = blockIdx.x, t = threadIdx.x;
    if (b < 32) {
        int i = b * 256 + t;
        if (ei[2 * i + 1] != 0) g_is64 = 0;
        return;
    }
    b -= 32;
    if (b < 4096) {
        split4(x, b * 256 + t, g_xh, g_xl);
    } else if (b < 4608) {
        wsplit1(W1, g_w1h, g_w1l, DIN, H1D, (b - 4096) * 256 + t);
    } else if (b < 4736) {
        wsplit1(W2, g_w2h, g_w2l, H1D, LATD, (b - 4608) * 256 + t);
    } else if (b < 4800) {
        wsplit1(Wmu, g_whh, g_whl, LATD, LATD, (b - 4736) * 256 + t);
    } else {
        wsplit1(Wlv, g_whh + LATD * LATD, g_whl + LATD * LATD, LATD, LATD,
                (b - 4800) * 256 + t);
    }
}

__device__ __forceinline__ int edge_val(const int* ei, int idx) {
    return g_is64 ? ei[2 * idx] : ei[idx];
}

// ---------------- launch 3: degree count ------------------------------------
__global__ void k_count(const int* __restrict__ ei) {
    int e = blockIdx.x * blockDim.x + threadIdx.x;
    if (e >= EE) return;
    int c = edge_val(ei, EE + e);
    atomicAdd(&g_cnt[c], 1);
}

// ---------------- hierarchical scan ------------------------------------------
__global__ void k_scan_a() {
    __shared__ int ws[8];
    int t = threadIdx.x, lane = t & 31, w = t >> 5;
    int i = blockIdx.x * 256 + t;
    int c = g_cnt[i];
    int v = c;
#pragma unroll
    for (int d = 1; d < 32; d <<= 1) {
        int u = __shfl_up_sync(0xffffffff, v, d);
        if (lane >= d) v += u;
    }
    if (lane == 31) ws[w] = v;
    __syncthreads();
    if (t < 8) {
        int x = ws[t];
#pragma unroll
        for (int d = 1; d < 8; d <<= 1) {
            int u = __shfl_up_sync(0xff, x, d);
            if (t >= d) x += u;
        }
        ws[t] = x;
    }
    __syncthreads();
    int excl = (w ? ws[w - 1] : 0) + v - c;
    g_off[i] = excl;
    g_dis[i] = rsqrtf((float)(c + 2));
    if (t == 255) g_bsum[blockIdx.x] = excl + c;
}

__global__ void k_scan_b() {
    int t = threadIdx.x;
    int c = g_bsum[t];
    int v = c;
#pragma unroll
    for (int d = 1; d < 32; d <<= 1) {
        int u = __shfl_up_sync(0xffffffff, v, d);
        if (t >= d) v += u;
    }
    g_boff[t] = v - c;
    if (t == 31) g_off[NN] = v;
}

__global__ void k_scan_c() {
    int i = blockIdx.x * 256 + threadIdx.x;
    int o = g_off[i] + g_boff[blockIdx.x];
    g_off[i] = o;
    g_cur[i] = o;
}

__global__ void k_fill(const int* __restrict__ ei) {
    int e = blockIdx.x * blockDim.x + threadIdx.x;
    if (e >= EE) return;
    int r = edge_val(ei, e);
    int c = edge_val(ei, EE + e);
    int p = atomicAdd(&g_cur[c], 1);
    g_csr[p] = r;
}

// ---------------- neighborhood aggregation (dis applied in gather) ----------
__global__ void k_agg(const float* __restrict__ hs, const float* __restrict__ bias,
                      __nv_bfloat16* __restrict__ zh, __nv_bfloat16* __restrict__ zl,
                      int F, int relu)
{
    __shared__ int   sj[256];
    __shared__ float sd[256];
    int i = blockIdx.x;
    int f = threadIdx.x;
    float di = g_dis[i];
    float a0 = 2.f * di * hs[(size_t)i * F + f], a1 = 0.f, a2 = 0.f, a3 = 0.f;
    int s = g_off[i], e = g_off[i + 1];
    for (int base = s; base < e; base += blockDim.x) {
        int m = min((int)blockDim.x, e - base);
        __syncthreads();
        if (f < m) {
            int j = g_csr[base + f];
            sj[f] = j;
            sd[f] = g_dis[j];
        }
        __syncthreads();
        int p = 0;
        for (; p + 4 <= m; p += 4) {
            float v0 = hs[(size_t)sj[p + 0] * F + f];
            float v1 = hs[(size_t)sj[p + 1] * F + f];
            float v2 = hs[(size_t)sj[p + 2] * F + f];
            float v3 = hs[(size_t)sj[p + 3] * F + f];
            a0 = fmaf(sd[p + 0], v0, a0);
            a1 = fmaf(sd[p + 1], v1, a1);
            a2 = fmaf(sd[p + 2], v2, a2);
            a3 = fmaf(sd[p + 3], v3, a3);
        }
        for (; p < m; p++) a0 = fmaf(sd[p], hs[(size_t)sj[p] * F + f], a0);
    }
    float v = di * ((a0 + a1) + (a2 + a3)) + bias[f];
    if (relu) v = fmaxf(v, 0.f);
    __nv_bfloat16 h, l;
    split1(v, h, l);
    zh[(size_t)i * F + f] = h;
    zl[(size_t)i * F + f] = l;
}

// ---------------- mma.sync helpers ------------------------------------------
__device__ __forceinline__ uint32_t smem_u32(const void* p) {
    uint32_t a;
    asm("{ .reg .u64 t; cvta.to.shared.u64 t, %1; cvt.u32.u64 %0, t; }" : "=r"(a) : "l"(p));
    return a;
}

__device__ __forceinline__ void ldsm_x4(uint32_t* r, uint32_t addr) {
    asm volatile("ldmatrix.sync.aligned.m8n8.x4.shared.b16 {%0,%1,%2,%3}, [%4];"
                 : "=r"(r[0]), "=r"(r[1]), "=r"(r[2]), "=r"(r[3]) : "r"(addr));
}

__device__ __forceinline__ void mma16816(float* d, const uint32_t* a, const uint32_t* b) {
    asm volatile("mma.sync.aligned.m16n8k16.row.col.f32.bf16.bf16.f32 "
                 "{%0,%1,%2,%3}, {%4,%5,%6,%7}, {%8,%9}, {%0,%1,%2,%3};"
                 : "+f"(d[0]), "+f"(d[1]), "+f"(d[2]), "+f"(d[3])
                 : "r"(a[0]), "r"(a[1]), "r"(a[2]), "r"(a[3]), "r"(b[0]), "r"(b[1]));
}

__device__ __forceinline__ void cpa16(uint32_t saddr, const void* g) {
    asm volatile("cp.async.cg.shared.global [%0], [%1], 16;"
                 :: "r"(saddr), "l"(g) : "memory");
}
#define CP_COMMIT() asm volatile("cp.async.commit_group;" ::: "memory")
#define CP_WAIT0()  asm volatile("cp.async.wait_group 0;" ::: "memory")
#define CP_WAIT1()  asm volatile("cp.async.wait_group 1;" ::: "memory")

#define TP        136                     // adj tile pitch (bf16)
#define TP2       (TP * 2)
#define TILE_B    (128 * TP2)             // 34816
#define ADJ_SMEM  (3 * TILE_B)            // 104448 (occ 2)

#define SP        72                      // gemm sub-tile pitch (bf16), 144B rows
#define SPB       (SP * 2)
#define STILE_B   (128 * SPB)             // 18432
#define GEMM_SMEM (8 * STILE_B)           // 147456 (2 stages x 4 operands)

// warp: 32(m) x 64(n), KS k-steps over a TPP-pitch tile
template<int TPP, int KS>
__device__ __forceinline__ void mma_pass_t(uint32_t sA, uint32_t sB, int m_w, int n_w,
                                           float d[2][8][4], int lane) {
    uint32_t a_base = sA + ((m_w + (lane & 15)) * TPP + (lane >> 4) * 8) * 2;
    int bmi = lane >> 3;
    uint32_t b_base = sB + ((n_w + ((bmi >> 1) * 8) + (lane & 7)) * TPP + (bmi & 1) * 8) * 2;
#pragma unroll
    for (int kk = 0; kk < KS; kk++) {
        int k0 = kk * 16;
        uint32_t a[2][4];
        ldsm_x4(a[0], a_base + k0 * 2);
        ldsm_x4(a[1], a_base + (16 * TPP + k0) * 2);
        uint32_t b[4][4];
#pragma unroll
        for (int np = 0; np < 4; np++)
            ldsm_x4(b[np], b_base + (np * 16 * TPP + k0) * 2);
#pragma unroll
        for (int mi = 0; mi < 2; mi++)
#pragma unroll
            for (int np = 0; np < 4; np++) {
                mma16816(d[mi][np * 2 + 0], a[mi], &b[np][0]);
                mma16816(d[mi][np * 2 + 1], a[mi], &b[np][2]);
            }
    }
}

// cp.async a 128-row x 64-col bf16 sub-tile (row length K, col offset kc)
__device__ __forceinline__ void load_sub(const __nv_bfloat16* g, int row0, int K,
                                         int kc, uint32_t dst) {
    int tid = threadIdx.x;
#pragma unroll
    for (int q = 0; q < 4; q++) {
        int idx = q * 256 + tid;          // 0..1023 : 128 rows x 8 16B-chunks
        int r = idx >> 3, c = idx & 7;
        cpa16(dst + r * SPB + c * 16, g + (size_t)(row0 + r) * K + kc + c * 8);
    }
}

// cp.async 128x128 bf16 tile (contiguous rows, pitch TP) — adj
__device__ __forceinline__ void load_tile_cpa(const __nv_bfloat16* g, int rowblk,
                                              uint32_t s_u32) {
    const uint4* src = (const uint4*)(g + (size_t)rowblk * 128 * 128);
    int tid = threadIdx.x;
#pragma unroll
    for (int q = 0; q < 8; q++) {
        int idx = q * 256 + tid;
        int r = idx >> 4, c = idx & 15;
        cpa16(s_u32 + r * TP2 + c * 16, src + idx);
    }
}

// ---------------- unified bf16-split HMMA GEMM (cp.async pipelined) ----------
// 64-wide K sub-chunks, double buffered; 3 passes per sub-chunk.
__global__ void __launch_bounds__(256, 1)
k_gemm_tc(const __nv_bfloat16* __restrict__ Ah, const __nv_bfloat16* __restrict__ Al,
          const __nv_bfloat16* __restrict__ Bh, const __nv_bfloat16* __restrict__ Bl,
          int K, int Ncols,
          float* __restrict__ Cout,
          int head,
          float* __restrict__ muF, float* __restrict__ lvF,
          const float* __restrict__ bmu, const float* __restrict__ blv,
          __nv_bfloat16* __restrict__ ph, __nv_bfloat16* __restrict__ pl)
{
    extern __shared__ __align__(16) char smem[];
    uint32_t sb = smem_u32(smem);
    // stage s, operand o (0=Ah,1=Al,2=Bh,3=Bl): sb + (s*4+o)*STILE_B

    int tid = threadIdx.x, wid = tid >> 5, lane = tid & 31;
    int m_w = (wid & 3) * 32, n_w = (wid >> 2) * 64;
    int bm = blockIdx.y * 128, bn = blockIdx.x * 128;

    float d[2][8][4];
#pragma unroll
    for (int mi = 0; mi < 2; mi++)
#pragma unroll
        for (int ni = 0; ni < 8; ni++)
#pragma unroll
            for (int q = 0; q < 4; q++) d[mi][ni][q] = 0.f;

    int nsub = K >> 6;
    // prefetch sub 0 into stage 0
    load_sub(Ah, bm, K, 0, sb + 0 * STILE_B);
    load_sub(Al, bm, K, 0, sb + 1 * STILE_B);
    load_sub(Bh, bn, K, 0, sb + 2 * STILE_B);
    load_sub(Bl, bn, K, 0, sb + 3 * STILE_B);
    CP_COMMIT();

    for (int s = 0; s < nsub; s++) {
        int cur = s & 1, nxt = cur ^ 1;
        if (s + 1 < nsub) {
            int kc = (s + 1) << 6;
            load_sub(Ah, bm, K, kc, sb + (nxt * 4 + 0) * STILE_B);
            load_sub(Al, bm, K, kc, sb + (nxt * 4 + 1) * STILE_B);
            load_sub(Bh, bn, K, kc, sb + (nxt * 4 + 2) * STILE_B);
            load_sub(Bl, bn, K, kc, sb + (nxt * 4 + 3) * STILE_B);
            CP_COMMIT();
            CP_WAIT1();
        } else {
            CP_WAIT0();
        }
        __syncthreads();
        uint32_t uAh = sb + (cur * 4 + 0) * STILE_B;
        uint32_t uAl = sb + (cur * 4 + 1) * STILE_B;
        uint32_t uBh = sb + (cur * 4 + 2) * STILE_B;
        uint32_t uBl = sb + (cur * 4 + 3) * STILE_B;
        mma_pass_t<SP, 4>(uAh, uBh, m_w, n_w, d, lane);
        mma_pass_t<SP, 4>(uAh, uBl, m_w, n_w, d, lane);
        mma_pass_t<SP, 4>(uAl, uBh, m_w, n_w, d, lane);
        __syncthreads();
    }

    int g4 = lane >> 2, tq = lane & 3;
    if (!head) {
#pragma unroll
        for (int mi = 0; mi < 2; mi++) {
            int r0 = bm + m_w + mi * 16 + g4;
#pragma unroll
            for (int ni = 0; ni < 8; ni++) {
                int c = bn + n_w + ni * 8 + tq * 2;
                *(float2*)&Cout[(size_t)r0 * Ncols + c] =
                    make_float2(d[mi][ni][0], d[mi][ni][1]);
                *(float2*)&Cout[(size_t)(r0 + 8) * Ncols + c] =
                    make_float2(d[mi][ni][2], d[mi][ni][3]);
            }
        }
    } else {
        bool is_mu = (blockIdx.x == 0);
        float* F = is_mu ? muF : lvF;
        const float* bias = is_mu ? bmu : blv;
#pragma unroll
        for (int mi = 0; mi < 2; mi++) {
            int r0 = bm + m_w + mi * 16 + g4;
#pragma unroll
            for (int ni = 0; ni < 8; ni++) {
                int c = n_w + ni * 8 + tq * 2;
                float b0 = bias[c], b1 = bias[c + 1];
                float v00 = d[mi][ni][0] + b0, v01 = d[mi][ni][1] + b1;
                float v10 = d[mi][ni][2] + b0, v11 = d[mi][ni][3] + b1;
                *(float2*)&F[(size_t)r0 * LATD + c]       = make_float2(v00, v01);
                *(float2*)&F[(size_t)(r0 + 8) * LATD + c] = make_float2(v10, v11);
                if (is_mu) {
                    __nv_bfloat16 h0, h1, h2, h3, l0, l1, l2, l3;
                    split1(v00, h0, l0); split1(v01, h1, l1);
                    split1(v10, h2, l2); split1(v11, h3, l3);
                    uint32_t hv0 = ((uint32_t)__bfloat16_as_ushort(h1) << 16) | __bfloat16_as_ushort(h0);
                    uint32_t hv1 = ((uint32_t)__bfloat16_as_ushort(h3) << 16) | __bfloat16_as_ushort(h2);
                    uint32_t lv0 = ((uint32_t)__bfloat16_as_ushort(l1) << 16) | __bfloat16_as_ushort(l0);
                    uint32_t lv1 = ((uint32_t)__bfloat16_as_ushort(l3) << 16) | __bfloat16_as_ushort(l2);
                    *(uint32_t*)&ph[(size_t)r0 * LATD + c]       = hv0;
                    *(uint32_t*)&ph[(size_t)(r0 + 8) * LATD + c] = hv1;
                    *(uint32_t*)&pl[(size_t)r0 * LATD + c]       = lv0;
                    *(uint32_t*)&pl[(size_t)(r0 + 8) * LATD + c] = lv1;
                }
            }
        }
    }
}

// ---------------- adj = sigmoid(mu @ mu^T), cp.async-overlapped --------------
__global__ void __launch_bounds__(256, 2)
k_adj_mma(const __nv_bfloat16* __restrict__ Ah, const __nv_bfloat16* __restrict__ Al,
          float* __restrict__ C)
{
    extern __shared__ __align__(16) char smem[];
    char* sA  = smem;
    char* sBh = smem + TILE_B;
    char* sBl = smem + 2 * TILE_B;
    uint32_t uA = smem_u32(sA), uBh = smem_u32(sBh), uBl = smem_u32(sBl);

    int tid = threadIdx.x, wid = tid >> 5, lane = tid & 31;
    int m_w = (wid & 3) * 32, n_w = (wid >> 2) * 64;

    int t = blockIdx.x, bi = 0;
    while (t >= 64 - bi) { t -= 64 - bi; bi++; }
    int bj = bi + t;

    float d[2][8][4];
#pragma unroll
    for (int mi = 0; mi < 2; mi++)
#pragma unroll
        for (int ni = 0; ni < 8; ni++)
#pragma unroll
            for (int q = 0; q < 4; q++) d[mi][ni][q] = 0.f;

    load_tile_cpa(Ah, bi, uA);
    load_tile_cpa(Ah, bj, uBh);
    load_tile_cpa(Al, bj, uBl);
    CP_COMMIT();
    CP_WAIT0();
    __syncthreads();

    mma_pass_t<TP, 8>(uA, uBl, m_w, n_w, d, lane);   // Ah_i · Al_j^T
    __syncthreads();
    load_tile_cpa(Al, bi, uBl);                       // async reload, overlapped
    CP_COMMIT();
    mma_pass_t<TP, 8>(uA, uBh, m_w, n_w, d, lane);   // Ah_i · Ah_j^T
    CP_WAIT0();
    __syncthreads();
    mma_pass_t<TP, 8>(uBl, uBh, m_w, n_w, d, lane);  // Al_i · Ah_j^T

#pragma unroll
    for (int mi = 0; mi < 2; mi++)
#pragma unroll
        for (int ni = 0; ni < 8; ni++)
#pragma unroll
            for (int q = 0; q < 4; q++)
                d[mi][ni][q] = 1.f / (1.f + __expf(-d[mi][ni][q]));

    int g4 = lane >> 2, tq = lane & 3;

#pragma unroll
    for (int mi = 0; mi < 2; mi++) {
        size_t r0 = (size_t)(bi * 128 + m_w + mi * 16 + g4);
#pragma unroll
        for (int ni = 0; ni < 8; ni++) {
            size_t cc = (size_t)(bj * 128 + n_w + ni * 8 + tq * 2);
            *(float2*)&C[r0 * NN + cc]       = make_float2(d[mi][ni][0], d[mi][ni][1]);
            *(float2*)&C[(r0 + 8) * NN + cc] = make_float2(d[mi][ni][2], d[mi][ni][3]);
        }
    }

    if (bi != bj) {
        __syncthreads();
        float* T = (float*)smem;
#pragma unroll
        for (int mi = 0; mi < 2; mi++) {
            int r = m_w + mi * 16 + g4;
#pragma unroll
            for (int ni = 0; ni < 8; ni++) {
                int c = n_w + ni * 8 + tq * 2;
                T[r * 129 + c]           = d[mi][ni][0];
                T[r * 129 + c + 1]       = d[mi][ni][1];
                T[(r + 8) * 129 + c]     = d[mi][ni][2];
                T[(r + 8) * 129 + c + 1] = d[mi][ni][3];
            }
        }
        __syncthreads();
#pragma unroll
        for (int q = 0; q < 64; q++) {
            int lin = q * 256 + tid;
            int cc = lin >> 7, rr = lin & 127;
            C[(size_t)(bj * 128 + cc) * NN + bi * 128 + rr] = T[rr * 129 + cc];
        }
    }
}

// ---------------- launch ----------------------------------------------------
extern "C" void kernel_launch(void* const* d_in, const int* in_sizes, int n_in,
                              void* d_out, int out_size)
{
    const float* x   = (const float*)d_in[0];
    const int*   ei  = (const int*)d_in[1];
    const float* W1  = (const float*)d_in[2];
    const float* b1  = (const float*)d_in[3];
    const float* W2  = (const float*)d_in[4];
    const float* b2  = (const float*)d_in[5];
    const float* Wmu = (const float*)d_in[6];
    const float* bmu = (const float*)d_in[7];
    const float* Wlv = (const float*)d_in[8];
    const float* blv = (const float*)d_in[9];

    float* out = (float*)d_out;
    float* mu  = out + (size_t)NN * NN;
    float* lv  = mu + (size_t)NN * LATD;

    float *p_hs1, *p_hs2;
    __nv_bfloat16 *p_xh, *p_xl, *p_z1h, *p_z1l, *p_z2h, *p_z2l, *p_muh, *p_mul;
    __nv_bfloat16 *p_w1h, *p_w1l, *p_w2h, *p_w2l, *p_whh, *p_whl;
    cudaGetSymbolAddress((void**)&p_hs1, g_hs1);
    cudaGetSymbolAddress((void**)&p_hs2, g_hs2);
    cudaGetSymbolAddress((void**)&p_xh,  g_xh);
    cudaGetSymbolAddress((void**)&p_xl,  g_xl);
    cudaGetSymbolAddress((void**)&p_z1h, g_z1h);
    cudaGetSymbolAddress((void**)&p_z1l, g_z1l);
    cudaGetSymbolAddress((void**)&p_z2h, g_z2h);
    cudaGetSymbolAddress((void**)&p_z2l, g_z2l);
    cudaGetSymbolAddress((void**)&p_muh, g_muh);
    cudaGetSymbolAddress((void**)&p_mul, g_mul);
    cudaGetSymbolAddress((void**)&p_w1h, g_w1h);
    cudaGetSymbolAddress((void**)&p_w1l, g_w1l);
    cudaGetSymbolAddress((void**)&p_w2h, g_w2h);
    cudaGetSymbolAddress((void**)&p_w2l, g_w2l);
    cudaGetSymbolAddress((void**)&p_whh, g_whh);
    cudaGetSymbolAddress((void**)&p_whl, g_whl);

    cudaFuncSetAttribute(k_adj_mma, cudaFuncAttributeMaxDynamicSharedMemorySize, ADJ_SMEM);
    cudaFuncSetAttribute(k_gemm_tc, cudaFuncAttributeMaxDynamicSharedMemorySize, GEMM_SMEM);

    // 1-3: init, detect+prep, count  (GEMM1 stays launch #4 for ncu)
    k_init   <<<8, 1024>>>();
    k_detprep<<<4896, 256>>>(ei, x, W1, W2, Wmu, Wlv);
    k_count  <<<EE / 256, 256>>>(ei);

    // 4: layer-1 GEMM
    k_gemm_tc<<<dim3(H1D / 128, NN / 128), 256, GEMM_SMEM>>>(
        p_xh, p_xl, p_w1h, p_w1l, DIN, H1D, p_hs1, 0,
        nullptr, nullptr, nullptr, nullptr, nullptr, nullptr);

    // 5-8: scan + CSR fill
    k_scan_a<<<32, 256>>>();
    k_scan_b<<<1, 32>>>();
    k_scan_c<<<32, 256>>>();
    k_fill  <<<EE / 256, 256>>>(ei);

    // 9: agg1 -> z1 planes (relu)
    k_agg<<<NN, H1D>>>(p_hs1, b1, p_z1h, p_z1l, H1D, 1);

    // 10-11: layer-2 GEMM + agg2
    k_gemm_tc<<<dim3(LATD / 128, NN / 128), 256, GEMM_SMEM>>>(
        p_z1h, p_z1l, p_w2h, p_w2l, H1D, LATD, p_hs2, 0,
        nullptr, nullptr, nullptr, nullptr, nullptr, nullptr);
    k_agg<<<NN, LATD>>>(p_hs2, b2, p_z2h, p_z2l, LATD, 0);

    // 12: fused heads
    k_gemm_tc<<<dim3(2, NN / 128), 256, GEMM_SMEM>>>(
        p_z2h, p_z2l, p_whh, p_whl, LATD, 2 * LATD, nullptr, 1,
        mu, lv, bmu, blv, p_muh, p_mul);

    // 13: adj = sigmoid(mu @ mu^T)
    k_adj_mma<<<2080, 256, ADJ_SMEM>>>(p_muh, p_mul, out);
}

// round 14
// speedup vs baseline: 2.1524x; 1.0001x over previous
#include <cuda_runtime.h>
#include <cuda_bf16.h>
#include <math.h>
#include <stdint.h>

#define NN   8192
#define EE   262144
#define DIN  512
#define H1D  256
#define LATD 128

// ---------------- scratch (device globals; no allocation allowed) ----------
__device__ int   g_is64;
__device__ int   g_cnt[NN];
__device__ int   g_off[NN + 1];
__device__ int   g_cur[NN];
__device__ int   g_bsum[32];
__device__ int   g_boff[32];
__device__ int   g_csr[EE];
__device__ float g_dis[NN];
__device__ float g_hs1[NN * H1D];
__device__ float g_hs2[NN * LATD];
__device__ __nv_bfloat16 g_xh [NN * DIN],  g_xl [NN * DIN];
__device__ __nv_bfloat16 g_z1h[NN * H1D],  g_z1l[NN * H1D];
__device__ __nv_bfloat16 g_z2h[NN * LATD], g_z2l[NN * LATD];
__device__ __nv_bfloat16 g_muh[NN * LATD], g_mul[NN * LATD];
__device__ __nv_bfloat16 g_w1h[H1D * DIN],  g_w1l[H1D * DIN];
__device__ __nv_bfloat16 g_w2h[LATD * H1D], g_w2l[LATD * H1D];
__device__ __nv_bfloat16 g_whh[2 * LATD * LATD], g_whl[2 * LATD * LATD];

// ---------------- split helpers ---------------------------------------------
__device__ __forceinline__ void split1(float v, __nv_bfloat16& h, __nv_bfloat16& l) {
    h = __float2bfloat16(v);
    l = __float2bfloat16(v - __bfloat162float(h));
}

__device__ __forceinline__ void split4(const float* src, int i,
                                       __nv_bfloat16* ph, __nv_bfloat16* pl) {
    float4 v = ((const float4*)src)[i];
    __nv_bfloat16 h0, h1, h2, h3, l0, l1, l2, l3;
    split1(v.x, h0, l0); split1(v.y, h1, l1); split1(v.z, h2, l2); split1(v.w, h3, l3);
    uint2 hv, lv;
    hv.x = ((uint32_t)__bfloat16_as_ushort(h1) << 16) | __bfloat16_as_ushort(h0);
    hv.y = ((uint32_t)__bfloat16_as_ushort(h3) << 16) | __bfloat16_as_ushort(h2);
    lv.x = ((uint32_t)__bfloat16_as_ushort(l1) << 16) | __bfloat16_as_ushort(l0);
    lv.y = ((uint32_t)__bfloat16_as_ushort(l3) << 16) | __bfloat16_as_ushort(l2);
    ((uint2*)ph)[i] = hv;
    ((uint2*)pl)[i] = lv;
}

__device__ __forceinline__ void wsplit1(const float* W, __nv_bfloat16* outh,
                                        __nv_bfloat16* outl, int Kdim, int Ndim, int idx) {
    int k = idx / Ndim, n = idx % Ndim;
    __nv_bfloat16 h, l;
    split1(W[idx], h, l);
    outh[(size_t)n * Kdim + k] = h;
    outl[(size_t)n * Kdim + k] = l;
}

// ---------------- launch 1 ----------------------------------------------------
__global__ void k_init() {
    int i = blockIdx.x * blockDim.x + threadIdx.x;
    if (i < NN) g_cnt[i] = 0;
    if (i == 0) g_is64 = 1;
}

// ---------------- launch 2: edge-width detect + all operand prep ------------
__global__ void k_detprep(const int* __restrict__ ei, const float* __restrict__ x,
                          const float* __restrict__ W1, const float* __restrict__ W2,
                          const float* __restrict__ Wmu, const float* __restrict__ Wlv) {
    int b = blockIdx.x, t = threadIdx.x;
    if (b < 32) {
        int i = b * 256 + t;
        if (ei[2 * i + 1] != 0) g_is64 = 0;
        return;
    }
    b -= 32;
    if (b < 4096) {
        split4(x, b * 256 + t, g_xh, g_xl);
    } else if (b < 4608) {
        wsplit1(W1, g_w1h, g_w1l, DIN, H1D, (b - 4096) * 256 + t);
    } else if (b < 4736) {
        wsplit1(W2, g_w2h, g_w2l, H1D, LATD, (b - 4608) * 256 + t);
    } else if (b < 4800) {
        wsplit1(Wmu, g_whh, g_whl, LATD, LATD, (b - 4736) * 256 + t);
    } else {
        wsplit1(Wlv, g_whh + LATD * LATD, g_whl + LATD * LATD, LATD, LATD,
                (b - 4800) * 256 + t);
    }
}

__device__ __forceinline__ int edge_val(const int* ei, int idx) {
    return g_is64 ? ei[2 * idx] : ei[idx];
}

// ---------------- launch 3: degree count ------------------------------------
__global__ void k_count(const int* __restrict__ ei) {
    int e = blockIdx.x * blockDim.x + threadIdx.x;
    if (e >= EE) return;
    int c = edge_val(ei, EE + e);
    atomicAdd(&g_cnt[c], 1);
}

// ---------------- hierarchical scan ------------------------------------------
__global__ void k_scan_a() {
    __shared__ int ws[8];
    int t = threadIdx.x, lane = t & 31, w = t >> 5;
    int i = blockIdx.x * 256 + t;
    int c = g_cnt[i];
    int v = c;
#pragma unroll
    for (int d = 1; d < 32; d <<= 1) {
        int u = __shfl_up_sync(0xffffffff, v, d);
        if (lane >= d) v += u;
    }
    if (lane == 31) ws[w] = v;
    __syncthreads();
    if (t < 8) {
        int x = ws[t];
#pragma unroll
        for (int d = 1; d < 8; d <<= 1) {
            int u = __shfl_up_sync(0xff, x, d);
            if (t >= d) x += u;
        }
        ws[t] = x;
    }
    __syncthreads();
    int excl = (w ? ws[w - 1] : 0) + v - c;
    g_off[i] = excl;
    g_dis[i] = rsqrtf((float)(c + 2));
    if (t == 255) g_bsum[blockIdx.x] = excl + c;
}

__global__ void k_scan_b() {
    int t = threadIdx.x;
    int c = g_bsum[t];
    int v = c;
#pragma unroll
    for (int d = 1; d < 32; d <<= 1) {
        int u = __shfl_up_sync(0xffffffff, v, d);
        if (t >= d) v += u;
    }
    g_boff[t] = v - c;
    if (t == 31) g_off[NN] = v;
}

__global__ void k_scan_c() {
    int i = blockIdx.x * 256 + threadIdx.x;
    int o = g_off[i] + g_boff[blockIdx.x];
    g_off[i] = o;
    g_cur[i] = o;
}

__global__ void k_fill(const int* __restrict__ ei) {
    int e = blockIdx.x * blockDim.x + threadIdx.x;
    if (e >= EE) return;
    int r = edge_val(ei, e);
    int c = edge_val(ei, EE + e);
    int p = atomicAdd(&g_cur[c], 1);
    g_csr[p] = r;
}

// ---------------- neighborhood aggregation ----------------------------------
__global__ void k_agg(const float* __restrict__ hs, const float* __restrict__ bias,
                      __nv_bfloat16* __restrict__ zh, __nv_bfloat16* __restrict__ zl,
                      int F, int relu)
{
    __shared__ int   sj[256];
    __shared__ float sd[256];
    int i = blockIdx.x;
    int f = threadIdx.x;
    float di = g_dis[i];
    float a0 = 2.f * di * hs[(size_t)i * F + f], a1 = 0.f, a2 = 0.f, a3 = 0.f;
    int s = g_off[i], e = g_off[i + 1];
    for (int base = s; base < e; base += blockDim.x) {
        int m = min((int)blockDim.x, e - base);
        __syncthreads();
        if (f < m) {
            int j = g_csr[base + f];
            sj[f] = j;
            sd[f] = g_dis[j];
        }
        __syncthreads();
        int p = 0;
        for (; p + 4 <= m; p += 4) {
            float v0 = hs[(size_t)sj[p + 0] * F + f];
            float v1 = hs[(size_t)sj[p + 1] * F + f];
            float v2 = hs[(size_t)sj[p + 2] * F + f];
            float v3 = hs[(size_t)sj[p + 3] * F + f];
            a0 = fmaf(sd[p + 0], v0, a0);
            a1 = fmaf(sd[p + 1], v1, a1);
            a2 = fmaf(sd[p + 2], v2, a2);
            a3 = fmaf(sd[p + 3], v3, a3);
        }
        for (; p < m; p++) a0 = fmaf(sd[p], hs[(size_t)sj[p] * F + f], a0);
    }
    float v = di * ((a0 + a1) + (a2 + a3)) + bias[f];
    if (relu) v = fmaxf(v, 0.f);
    __nv_bfloat16 h, l;
    split1(v, h, l);
    zh[(size_t)i * F + f] = h;
    zl[(size_t)i * F + f] = l;
}

// ---------------- mma.sync helpers ------------------------------------------
__device__ __forceinline__ uint32_t smem_u32(const void* p) {
    uint32_t a;
    asm("{ .reg .u64 t; cvta.to.shared.u64 t, %1; cvt.u32.u64 %0, t; }" : "=r"(a) : "l"(p));
    return a;
}

__device__ __forceinline__ void ldsm_x4(uint32_t* r, uint32_t addr) {
    asm volatile("ldmatrix.sync.aligned.m8n8.x4.shared.b16 {%0,%1,%2,%3}, [%4];"
                 : "=r"(r[0]), "=r"(r[1]), "=r"(r[2]), "=r"(r[3]) : "r"(addr));
}

__device__ __forceinline__ void mma16816(float* d, const uint32_t* a, const uint32_t* b) {
    asm volatile("mma.sync.aligned.m16n8k16.row.col.f32.bf16.bf16.f32 "
                 "{%0,%1,%2,%3}, {%4,%5,%6,%7}, {%8,%9}, {%0,%1,%2,%3};"
                 : "+f"(d[0]), "+f"(d[1]), "+f"(d[2]), "+f"(d[3])
                 : "r"(a[0]), "r"(a[1]), "r"(a[2]), "r"(a[3]), "r"(b[0]), "r"(b[1]));
}

__device__ __forceinline__ void cpa16(uint32_t saddr, const void* g) {
    asm volatile("cp.async.cg.shared.global [%0], [%1], 16;"
                 :: "r"(saddr), "l"(g) : "memory");
}
#define CP_COMMIT() asm volatile("cp.async.commit_group;" ::: "memory")
#define CP_WAIT0()  asm volatile("cp.async.wait_group 0;" ::: "memory")
#define CP_WAIT1()  asm volatile("cp.async.wait_group 1;" ::: "memory")

#define TP        136                     // adj tile pitch (bf16)
#define TP2       (TP * 2)
#define TILE_B    (128 * TP2)             // 34816
#define ADJ_SMEM  (3 * TILE_B)            // 104448 (occ 2)

#define SP        72                      // gemm sub-tile pitch (bf16), 144B rows
#define SPB       (SP * 2)
#define ATILE_B   (64 * SPB)              // 9216  (A: 64 rows x 64 cols)
#define BTILE_B   (128 * SPB)             // 18432 (B: 128 rows x 64 cols)
#define STAGE_B   (2 * ATILE_B + 2 * BTILE_B)   // 55296
#define GEMM_SMEM (2 * STAGE_B)           // 110592 -> 2 CTAs/SM

// ---- adj warp pass: 32(m) x 64(n), 8 k-steps, pitch TP ----------------------
__device__ __forceinline__ void mma_pass_adj(uint32_t sA, uint32_t sB, int m_w, int n_w,
                                             float d[2][8][4], int lane) {
    uint32_t a_base = sA + ((m_w + (lane & 15)) * TP + (lane >> 4) * 8) * 2;
    int bmi = lane >> 3;
    uint32_t b_base = sB + ((n_w + ((bmi >> 1) * 8) + (lane & 7)) * TP + (bmi & 1) * 8) * 2;
#pragma unroll
    for (int kk = 0; kk < 8; kk++) {
        int k0 = kk * 16;
        uint32_t a[2][4];
        ldsm_x4(a[0], a_base + k0 * 2);
        ldsm_x4(a[1], a_base + (16 * TP + k0) * 2);
        uint32_t b[4][4];
#pragma unroll
        for (int np = 0; np < 4; np++)
            ldsm_x4(b[np], b_base + (np * 16 * TP + k0) * 2);
#pragma unroll
        for (int mi = 0; mi < 2; mi++)
#pragma unroll
            for (int np = 0; np < 4; np++) {
                mma16816(d[mi][np * 2 + 0], a[mi], &b[np][0]);
                mma16816(d[mi][np * 2 + 1], a[mi], &b[np][2]);
            }
    }
}

// ---- gemm warp pass: 16(m) x 64(n), 4 k-steps, pitch SP ---------------------
__device__ __forceinline__ void mma_pass_g(uint32_t sA, uint32_t sB, int m_w, int n_w,
                                           float d[8][4], int lane) {
    uint32_t a_base = sA + ((m_w + (lane & 15)) * SP + (lane >> 4) * 8) * 2;
    int bmi = lane >> 3;
    uint32_t b_base = sB + ((n_w + ((bmi >> 1) * 8) + (lane & 7)) * SP + (bmi & 1) * 8) * 2;
#pragma unroll
    for (int kk = 0; kk < 4; kk++) {
        int k0 = kk * 16;
        uint32_t a[4];
        ldsm_x4(a, a_base + k0 * 2);
        uint32_t b[4][4];
#pragma unroll
        for (int np = 0; np < 4; np++)
            ldsm_x4(b[np], b_base + (np * 16 * SP + k0) * 2);
#pragma unroll
        for (int np = 0; np < 4; np++) {
            mma16816(d[np * 2 + 0], a, &b[np][0]);
            mma16816(d[np * 2 + 1], a, &b[np][2]);
        }
    }
}

// cp.async sub-tiles: ROWS x 64 bf16 (row length K, col offset kc)
template<int ROWS>
__device__ __forceinline__ void load_sub(const __nv_bfloat16* g, int row0, int K,
                                         int kc, uint32_t dst) {
    int tid = threadIdx.x;
#pragma unroll
    for (int q = 0; q < ROWS / 32; q++) {
        int idx = q * 256 + tid;          // ROWS rows x 8 16B-chunks
        int r = idx >> 3, c = idx & 7;
        cpa16(dst + r * SPB + c * 16, g + (size_t)(row0 + r) * K + kc + c * 8);
    }
}

// cp.async 128x128 bf16 tile (contiguous rows, pitch TP) — adj
__device__ __forceinline__ void load_tile_cpa(const __nv_bfloat16* g, int rowblk,
                                              uint32_t s_u32) {
    const uint4* src = (const uint4*)(g + (size_t)rowblk * 128 * 128);
    int tid = threadIdx.x;
#pragma unroll
    for (int q = 0; q < 8; q++) {
        int idx = q * 256 + tid;
        int r = idx >> 4, c = idx & 15;
        cpa16(s_u32 + r * TP2 + c * 16, src + idx);
    }
}

// ---------------- unified bf16-split HMMA GEMM (64x128 CTA, occ 2) -----------
__global__ void __launch_bounds__(256, 2)
k_gemm_tc(const __nv_bfloat16* __restrict__ Ah, const __nv_bfloat16* __restrict__ Al,
          const __nv_bfloat16* __restrict__ Bh, const __nv_bfloat16* __restrict__ Bl,
          int K, int Ncols,
          float* __restrict__ Cout,
          int head,
          float* __restrict__ muF, float* __restrict__ lvF,
          const float* __restrict__ bmu, const float* __restrict__ blv,
          __nv_bfloat16* __restrict__ ph, __nv_bfloat16* __restrict__ pl)
{
    extern __shared__ __align__(16) char smem[];
    uint32_t sb = smem_u32(smem);
    // stage layout: [Ah(ATILE) Al(ATILE) Bh(BTILE) Bl(BTILE)] x 2 stages

    int tid = threadIdx.x, wid = tid >> 5, lane = tid & 31;
    int m_w = (wid & 3) * 16, n_w = (wid >> 2) * 64;
    int bm = blockIdx.y * 64, bn = blockIdx.x * 128;

    float d[8][4];
#pragma unroll
    for (int ni = 0; ni < 8; ni++)
#pragma unroll
        for (int q = 0; q < 4; q++) d[ni][q] = 0.f;

    int nsub = K >> 6;
    load_sub<64> (Ah, bm, K, 0, sb);
    load_sub<64> (Al, bm, K, 0, sb + ATILE_B);
    load_sub<128>(Bh, bn, K, 0, sb + 2 * ATILE_B);
    load_sub<128>(Bl, bn, K, 0, sb + 2 * ATILE_B + BTILE_B);
    CP_COMMIT();

    for (int s = 0; s < nsub; s++) {
        int cur = s & 1, nxt = cur ^ 1;
        if (s + 1 < nsub) {
            int kc = (s + 1) << 6;
            uint32_t st = sb + nxt * STAGE_B;
            load_sub<64> (Ah, bm, K, kc, st);
            load_sub<64> (Al, bm, K, kc, st + ATILE_B);
            load_sub<128>(Bh, bn, K, kc, st + 2 * ATILE_B);
            load_sub<128>(Bl, bn, K, kc, st + 2 * ATILE_B + BTILE_B);
            CP_COMMIT();
            CP_WAIT1();
        } else {
            CP_WAIT0();
        }
        __syncthreads();
        uint32_t st = sb + cur * STAGE_B;
        uint32_t uAh = st, uAl = st + ATILE_B;
        uint32_t uBh = st + 2 * ATILE_B, uBl = st + 2 * ATILE_B + BTILE_B;
        mma_pass_g(uAh, uBh, m_w, n_w, d, lane);
        mma_pass_g(uAh, uBl, m_w, n_w, d, lane);
        mma_pass_g(uAl, uBh, m_w, n_w, d, lane);
        __syncthreads();
    }

    int g4 = lane >> 2, tq = lane & 3;
    if (!head) {
        int r0 = bm + m_w + g4;
#pragma unroll
        for (int ni = 0; ni < 8; ni++) {
            int c = bn + n_w + ni * 8 + tq * 2;
            *(float2*)&Cout[(size_t)r0 * Ncols + c]       = make_float2(d[ni][0], d[ni][1]);
            *(float2*)&Cout[(size_t)(r0 + 8) * Ncols + c] = make_float2(d[ni][2], d[ni][3]);
        }
    } else {
        bool is_mu = (blockIdx.x == 0);
        float* F = is_mu ? muF : lvF;
        const float* bias = is_mu ? bmu : blv;
        int r0 = bm + m_w + g4;
#pragma unroll
        for (int ni = 0; ni < 8; ni++) {
            int c = n_w + ni * 8 + tq * 2;
            float b0 = bias[c], b1 = bias[c + 1];
            float v00 = d[ni][0] + b0, v01 = d[ni][1] + b1;
            float v10 = d[ni][2] + b0, v11 = d[ni][3] + b1;
            *(float2*)&F[(size_t)r0 * LATD + c]       = make_float2(v00, v01);
            *(float2*)&F[(size_t)(r0 + 8) * LATD + c] = make_float2(v10, v11);
            if (is_mu) {
                __nv_bfloat16 h0, h1, h2, h3, l0, l1, l2, l3;
                split1(v00, h0, l0); split1(v01, h1, l1);
                split1(v10, h2, l2); split1(v11, h3, l3);
                uint32_t hv0 = ((uint32_t)__bfloat16_as_ushort(h1) << 16) | __bfloat16_as_ushort(h0);
                uint32_t hv1 = ((uint32_t)__bfloat16_as_ushort(h3) << 16) | __bfloat16_as_ushort(h2);
                uint32_t lv0 = ((uint32_t)__bfloat16_as_ushort(l1) << 16) | __bfloat16_as_ushort(l0);
                uint32_t lv1 = ((uint32_t)__bfloat16_as_ushort(l3) << 16) | __bfloat16_as_ushort(l2);
                *(uint32_t*)&ph[(size_t)r0 * LATD + c]       = hv0;
                *(uint32_t*)&ph[(size_t)(r0 + 8) * LATD + c] = hv1;
                *(uint32_t*)&pl[(size_t)r0 * LATD + c]       = lv0;
                *(uint32_t*)&pl[(size_t)(r0 + 8) * LATD + c] = lv1;
            }
        }
    }
}

// ---------------- adj = sigmoid(mu @ mu^T), cp.async-overlapped --------------
__global__ void __launch_bounds__(256, 2)
k_adj_mma(const __nv_bfloat16* __restrict__ Ah, const __nv_bfloat16* __restrict__ Al,
          float* __restrict__ C)
{
    extern __shared__ __align__(16) char smem[];
    char* sA  = smem;
    char* sBh = smem + TILE_B;
    char* sBl = smem + 2 * TILE_B;
    uint32_t uA = smem_u32(sA), uBh = smem_u32(sBh), uBl = smem_u32(sBl);

    int tid = threadIdx.x, wid = tid >> 5, lane = tid & 31;
    int m_w = (wid & 3) * 32, n_w = (wid >> 2) * 64;

    int t = blockIdx.x, bi = 0;
    while (t >= 64 - bi) { t -= 64 - bi; bi++; }
    int bj = bi + t;

    float d[2][8][4];
#pragma unroll
    for (int mi = 0; mi < 2; mi++)
#pragma unroll
        for (int ni = 0; ni < 8; ni++)
#pragma unroll
            for (int q = 0; q < 4; q++) d[mi][ni][q] = 0.f;

    load_tile_cpa(Ah, bi, uA);
    load_tile_cpa(Ah, bj, uBh);
    load_tile_cpa(Al, bj, uBl);
    CP_COMMIT();
    CP_WAIT0();
    __syncthreads();

    mma_pass_adj(uA, uBl, m_w, n_w, d, lane);
    __syncthreads();
    load_tile_cpa(Al, bi, uBl);
    CP_COMMIT();
    mma_pass_adj(uA, uBh, m_w, n_w, d, lane);
    CP_WAIT0();
    __syncthreads();
    mma_pass_adj(uBl, uBh, m_w, n_w, d, lane);

#pragma unroll
    for (int mi = 0; mi < 2; mi++)
#pragma unroll
        for (int ni = 0; ni < 8; ni++)
#pragma unroll
            for (int q = 0; q < 4; q++)
                d[mi][ni][q] = 1.f / (1.f + __expf(-d[mi][ni][q]));

    int g4 = lane >> 2, tq = lane & 3;

#pragma unroll
    for (int mi = 0; mi < 2; mi++) {
        size_t r0 = (size_t)(bi * 128 + m_w + mi * 16 + g4);
#pragma unroll
        for (int ni = 0; ni < 8; ni++) {
            size_t cc = (size_t)(bj * 128 + n_w + ni * 8 + tq * 2);
            *(float2*)&C[r0 * NN + cc]       = make_float2(d[mi][ni][0], d[mi][ni][1]);
            *(float2*)&C[(r0 + 8) * NN + cc] = make_float2(d[mi][ni][2], d[mi][ni][3]);
        }
    }

    if (bi != bj) {
        __syncthreads();
        float* T = (float*)smem;
#pragma unroll
        for (int mi = 0; mi < 2; mi++) {
            int r = m_w + mi * 16 + g4;
#pragma unroll
            for (int ni = 0; ni < 8; ni++) {
                int c = n_w + ni * 8 + tq * 2;
                T[r * 129 + c]           = d[mi][ni][0];
                T[r * 129 + c + 1]       = d[mi][ni][1];
                T[(r + 8) * 129 + c]     = d[mi][ni][2];
                T[(r + 8) * 129 + c + 1] = d[mi][ni][3];
            }
        }
        __syncthreads();
#pragma unroll
        for (int q = 0; q < 64; q++) {
            int lin = q * 256 + tid;
            int cc = lin >> 7, rr = lin & 127;
            C[(size_t)(bj * 128 + cc) * NN + bi * 128 + rr] = T[rr * 129 + cc];
        }
    }
}

// ---------------- launch ----------------------------------------------------
extern "C" void kernel_launch(void* const* d_in, const int* in_sizes, int n_in,
                              void* d_out, int out_size)
{
    const float* x   = (const float*)d_in[0];
    const int*   ei  = (const int*)d_in[1];
    const float* W1  = (const float*)d_in[2];
    const float* b1  = (const float*)d_in[3];
    const float* W2  = (const float*)d_in[4];
    const float* b2  = (const float*)d_in[5];
    const float* Wmu = (const float*)d_in[6];
    const float* bmu = (const float*)d_in[7];
    const float* Wlv = (const float*)d_in[8];
    const float* blv = (const float*)d_in[9];

    float* out = (float*)d_out;
    float* mu  = out + (size_t)NN * NN;
    float* lv  = mu + (size_t)NN * LATD;

    float *p_hs1, *p_hs2;
    __nv_bfloat16 *p_xh, *p_xl, *p_z1h, *p_z1l, *p_z2h, *p_z2l, *p_muh, *p_mul;
    __nv_bfloat16 *p_w1h, *p_w1l, *p_w2h, *p_w2l, *p_whh, *p_whl;
    cudaGetSymbolAddress((void**)&p_hs1, g_hs1);
    cudaGetSymbolAddress((void**)&p_hs2, g_hs2);
    cudaGetSymbolAddress((void**)&p_xh,  g_xh);
    cudaGetSymbolAddress((void**)&p_xl,  g_xl);
    cudaGetSymbolAddress((void**)&p_z1h, g_z1h);
    cudaGetSymbolAddress((void**)&p_z1l, g_z1l);
    cudaGetSymbolAddress((void**)&p_z2h, g_z2h);
    cudaGetSymbolAddress((void**)&p_z2l, g_z2l);
    cudaGetSymbolAddress((void**)&p_muh, g_muh);
    cudaGetSymbolAddress((void**)&p_mul, g_mul);
    cudaGetSymbolAddress((void**)&p_w1h, g_w1h);
    cudaGetSymbolAddress((void**)&p_w1l, g_w1l);
    cudaGetSymbolAddress((void**)&p_w2h, g_w2h);
    cudaGetSymbolAddress((void**)&p_w2l, g_w2l);
    cudaGetSymbolAddress((void**)&p_whh, g_whh);
    cudaGetSymbolAddress((void**)&p_whl, g_whl);

    cudaFuncSetAttribute(k_adj_mma, cudaFuncAttributeMaxDynamicSharedMemorySize, ADJ_SMEM);
    cudaFuncSetAttribute(k_gemm_tc, cudaFuncAttributeMaxDynamicSharedMemorySize, GEMM_SMEM);

    // 1-3: init, detect+prep, count  (GEMM1 stays launch #4 for ncu)
    k_init   <<<8, 1024>>>();
    k_detprep<<<4896, 256>>>(ei, x, W1, W2, Wmu, Wlv);
    k_count  <<<EE / 256, 256>>>(ei);

    // 4: layer-1 GEMM  (64-row M tiles)
    k_gemm_tc<<<dim3(H1D / 128, NN / 64), 256, GEMM_SMEM>>>(
        p_xh, p_xl, p_w1h, p_w1l, DIN, H1D, p_hs1, 0,
        nullptr, nullptr, nullptr, nullptr, nullptr, nullptr);

    // 5-8: scan + CSR fill
    k_scan_a<<<32, 256>>>();
    k_scan_b<<<1, 32>>>();
    k_scan_c<<<32, 256>>>();
    k_fill  <<<EE / 256, 256>>>(ei);

    // 9: agg1 -> z1 planes (relu)
    k_agg<<<NN, H1D>>>(p_hs1, b1, p_z1h, p_z1l, H1D, 1);

    // 10-11: layer-2 GEMM + agg2
    k_gemm_tc<<<dim3(LATD / 128, NN / 64), 256, GEMM_SMEM>>>(
        p_z1h, p_z1l, p_w2h, p_w2l, H1D, LATD, p_hs2, 0,
        nullptr, nullptr, nullptr, nullptr, nullptr, nullptr);
    k_agg<<<NN, LATD>>>(p_hs2, b2, p_z2h, p_z2l, LATD, 0);

    // 12: fused heads
    k_gemm_tc<<<dim3(2, NN / 64), 256, GEMM_SMEM>>>(
        p_z2h, p_z2l, p_whh, p_whl, LATD, 2 * LATD, nullptr, 1,
        mu, lv, bmu, blv, p_muh, p_mul);

    // 13: adj = sigmoid(mu @ mu^T)
    k_adj_mma<<<2080, 256, ADJ_SMEM>>>(p_muh, p_mul, out);
}

// round 15
// speedup vs baseline: 2.1679x; 1.0072x over previous
#include <cuda_runtime.h>
#include <cuda_bf16.h>
#include <math.h>
#include <stdint.h>

#define NN   8192
#define EE   262144
#define DIN  512
#define H1D  256
#define LATD 128

// ---------------- scratch (device globals; no allocation allowed) ----------
__device__ int   g_is64;
__device__ int   g_cnt[NN];
__device__ int   g_off[NN + 1];
__device__ int   g_cur[NN];
__device__ int   g_bsum[32];
__device__ int   g_boff[32];
__device__ int   g_csr[EE];
__device__ float g_dis[NN];
__device__ float g_hs1[NN * H1D];
__device__ float g_hs2[NN * LATD];
__device__ __nv_bfloat16 g_xh [NN * DIN],  g_xl [NN * DIN];
__device__ __nv_bfloat16 g_z1h[NN * H1D],  g_z1l[NN * H1D];
__device__ __nv_bfloat16 g_z2h[NN * LATD], g_z2l[NN * LATD];
__device__ __nv_bfloat16 g_muh[NN * LATD], g_mul[NN * LATD];
__device__ __nv_bfloat16 g_w1h[H1D * DIN],  g_w1l[H1D * DIN];
__device__ __nv_bfloat16 g_w2h[LATD * H1D], g_w2l[LATD * H1D];
__device__ __nv_bfloat16 g_whh[2 * LATD * LATD], g_whl[2 * LATD * LATD];

// ---------------- split helpers ---------------------------------------------
__device__ __forceinline__ void split1(float v, __nv_bfloat16& h, __nv_bfloat16& l) {
    h = __float2bfloat16(v);
    l = __float2bfloat16(v - __bfloat162float(h));
}

__device__ __forceinline__ void split4(const float* src, int i,
                                       __nv_bfloat16* ph, __nv_bfloat16* pl) {
    float4 v = ((const float4*)src)[i];
    __nv_bfloat16 h0, h1, h2, h3, l0, l1, l2, l3;
    split1(v.x, h0, l0); split1(v.y, h1, l1); split1(v.z, h2, l2); split1(v.w, h3, l3);
    uint2 hv, lv;
    hv.x = ((uint32_t)__bfloat16_as_ushort(h1) << 16) | __bfloat16_as_ushort(h0);
    hv.y = ((uint32_t)__bfloat16_as_ushort(h3) << 16) | __bfloat16_as_ushort(h2);
    lv.x = ((uint32_t)__bfloat16_as_ushort(l1) << 16) | __bfloat16_as_ushort(l0);
    lv.y = ((uint32_t)__bfloat16_as_ushort(l3) << 16) | __bfloat16_as_ushort(l2);
    ((uint2*)ph)[i] = hv;
    ((uint2*)pl)[i] = lv;
}

__device__ __forceinline__ void wsplit1(const float* W, __nv_bfloat16* outh,
                                        __nv_bfloat16* outl, int Kdim, int Ndim, int idx) {
    int k = idx / Ndim, n = idx % Ndim;
    __nv_bfloat16 h, l;
    split1(W[idx], h, l);
    outh[(size_t)n * Kdim + k] = h;
    outl[(size_t)n * Kdim + k] = l;
}

// ---------------- launch 1 ----------------------------------------------------
__global__ void k_init() {
    int i = blockIdx.x * blockDim.x + threadIdx.x;
    if (i < NN) g_cnt[i] = 0;
    if (i == 0) g_is64 = 1;
}

// ---------------- launch 2: edge-width detect + all operand prep ------------
__global__ void k_detprep(const int* __restrict__ ei, const float* __restrict__ x,
                          const float* __restrict__ W1, const float* __restrict__ W2,
                          const float* __restrict__ Wmu, const float* __restrict__ Wlv) {
    int b = blockIdx.x, t = threadIdx.x;
    if (b < 32) {
        int i = b * 256 + t;
        if (ei[2 * i + 1] != 0) g_is64 = 0;
        return;
    }
    b -= 32;
    if (b < 4096) {
        split4(x, b * 256 + t, g_xh, g_xl);
    } else if (b < 4608) {
        wsplit1(W1, g_w1h, g_w1l, DIN, H1D, (b - 4096) * 256 + t);
    } else if (b < 4736) {
        wsplit1(W2, g_w2h, g_w2l, H1D, LATD, (b - 4608) * 256 + t);
    } else if (b < 4800) {
        wsplit1(Wmu, g_whh, g_whl, LATD, LATD, (b - 4736) * 256 + t);
    } else {
        wsplit1(Wlv, g_whh + LATD * LATD, g_whl + LATD * LATD, LATD, LATD,
                (b - 4800) * 256 + t);
    }
}

__device__ __forceinline__ int edge_val(const int* ei, int idx) {
    return g_is64 ? ei[2 * idx] : ei[idx];
}

// ---------------- launch 3: degree count ------------------------------------
__global__ void k_count(const int* __restrict__ ei) {
    int e = blockIdx.x * blockDim.x + threadIdx.x;
    if (e >= EE) return;
    int c = edge_val(ei, EE + e);
    atomicAdd(&g_cnt[c], 1);
}

// ---------------- hierarchical scan ------------------------------------------
__global__ void k_scan_a() {
    __shared__ int ws[8];
    int t = threadIdx.x, lane = t & 31, w = t >> 5;
    int i = blockIdx.x * 256 + t;
    int c = g_cnt[i];
    int v = c;
#pragma unroll
    for (int d = 1; d < 32; d <<= 1) {
        int u = __shfl_up_sync(0xffffffff, v, d);
        if (lane >= d) v += u;
    }
    if (lane == 31) ws[w] = v;
    __syncthreads();
    if (t < 8) {
        int x = ws[t];
#pragma unroll
        for (int d = 1; d < 8; d <<= 1) {
            int u = __shfl_up_sync(0xff, x, d);
            if (t >= d) x += u;
        }
        ws[t] = x;
    }
    __syncthreads();
    int excl = (w ? ws[w - 1] : 0) + v - c;
    g_off[i] = excl;
    g_dis[i] = rsqrtf((float)(c + 2));
    if (t == 255) g_bsum[blockIdx.x] = excl + c;
}

__global__ void k_scan_b() {
    int t = threadIdx.x;
    int c = g_bsum[t];
    int v = c;
#pragma unroll
    for (int d = 1; d < 32; d <<= 1) {
        int u = __shfl_up_sync(0xffffffff, v, d);
        if (t >= d) v += u;
    }
    g_boff[t] = v - c;
    if (t == 31) g_off[NN] = v;
}

__global__ void k_scan_c() {
    int i = blockIdx.x * 256 + threadIdx.x;
    int o = g_off[i] + g_boff[blockIdx.x];
    g_off[i] = o;
    g_cur[i] = o;
}

__global__ void k_fill(const int* __restrict__ ei) {
    int e = blockIdx.x * blockDim.x + threadIdx.x;
    if (e >= EE) return;
    int r = edge_val(ei, e);
    int c = edge_val(ei, EE + e);
    int p = atomicAdd(&g_cur[c], 1);
    g_csr[p] = r;
}

// ---------------- neighborhood aggregation ----------------------------------
__global__ void k_agg(const float* __restrict__ hs, const float* __restrict__ bias,
                      __nv_bfloat16* __restrict__ zh, __nv_bfloat16* __restrict__ zl,
                      int F, int relu)
{
    __shared__ int   sj[256];
    __shared__ float sd[256];
    int i = blockIdx.x;
    int f = threadIdx.x;
    float di = g_dis[i];
    float a0 = 2.f * di * hs[(size_t)i * F + f], a1 = 0.f, a2 = 0.f, a3 = 0.f;
    int s = g_off[i], e = g_off[i + 1];
    for (int base = s; base < e; base += blockDim.x) {
        int m = min((int)blockDim.x, e - base);
        __syncthreads();
        if (f < m) {
            int j = g_csr[base + f];
            sj[f] = j;
            sd[f] = g_dis[j];
        }
        __syncthreads();
        int p = 0;
        for (; p + 4 <= m; p += 4) {
            float v0 = hs[(size_t)sj[p + 0] * F + f];
            float v1 = hs[(size_t)sj[p + 1] * F + f];
            float v2 = hs[(size_t)sj[p + 2] * F + f];
            float v3 = hs[(size_t)sj[p + 3] * F + f];
            a0 = fmaf(sd[p + 0], v0, a0);
            a1 = fmaf(sd[p + 1], v1, a1);
            a2 = fmaf(sd[p + 2], v2, a2);
            a3 = fmaf(sd[p + 3], v3, a3);
        }
        for (; p < m; p++) a0 = fmaf(sd[p], hs[(size_t)sj[p] * F + f], a0);
    }
    float v = di * ((a0 + a1) + (a2 + a3)) + bias[f];
    if (relu) v = fmaxf(v, 0.f);
    __nv_bfloat16 h, l;
    split1(v, h, l);
    zh[(size_t)i * F + f] = h;
    zl[(size_t)i * F + f] = l;
}

// ---------------- mma.sync helpers ------------------------------------------
__device__ __forceinline__ uint32_t smem_u32(const void* p) {
    uint32_t a;
    asm("{ .reg .u64 t; cvta.to.shared.u64 t, %1; cvt.u32.u64 %0, t; }" : "=r"(a) : "l"(p));
    return a;
}

__device__ __forceinline__ void ldsm_x4(uint32_t* r, uint32_t addr) {
    asm volatile("ldmatrix.sync.aligned.m8n8.x4.shared.b16 {%0,%1,%2,%3}, [%4];"
                 : "=r"(r[0]), "=r"(r[1]), "=r"(r[2]), "=r"(r[3]) : "r"(addr));
}

__device__ __forceinline__ void mma16816(float* d, const uint32_t* a, const uint32_t* b) {
    asm volatile("mma.sync.aligned.m16n8k16.row.col.f32.bf16.bf16.f32 "
                 "{%0,%1,%2,%3}, {%4,%5,%6,%7}, {%8,%9}, {%0,%1,%2,%3};"
                 : "+f"(d[0]), "+f"(d[1]), "+f"(d[2]), "+f"(d[3])
                 : "r"(a[0]), "r"(a[1]), "r"(a[2]), "r"(a[3]), "r"(b[0]), "r"(b[1]));
}

__device__ __forceinline__ void cpa16(uint32_t saddr, const void* g) {
    asm volatile("cp.async.cg.shared.global [%0], [%1], 16;"
                 :: "r"(saddr), "l"(g) : "memory");
}
#define CP_COMMIT() asm volatile("cp.async.commit_group;" ::: "memory")
#define CP_WAIT0()  asm volatile("cp.async.wait_group 0;" ::: "memory")
#define CP_WAIT1()  asm volatile("cp.async.wait_group 1;" ::: "memory")

#define TP        136                     // adj tile pitch (bf16)
#define TP2       (TP * 2)
#define TILE_B    (128 * TP2)             // 34816
#define ADJ_SMEM  (3 * TILE_B)            // 104448 (occ 2)

#define SP        72                      // gemm sub-tile pitch (bf16), 144B rows
#define SPB       (SP * 2)
#define STILE_B   (128 * SPB)             // 18432 (128 rows x 64 cols)
#define STAGE_B   (4 * STILE_B)           // 73728
#define GEMM_SMEM (2 * STAGE_B)           // 147456 (occ 1)

// ---- adj warp pass: 32(m) x 64(n), 8 k-steps, pitch TP ----------------------
__device__ __forceinline__ void mma_pass_adj(uint32_t sA, uint32_t sB, int m_w, int n_w,
                                             float d[2][8][4], int lane) {
    uint32_t a_base = sA + ((m_w + (lane & 15)) * TP + (lane >> 4) * 8) * 2;
    int bmi = lane >> 3;
    uint32_t b_base = sB + ((n_w + ((bmi >> 1) * 8) + (lane & 7)) * TP + (bmi & 1) * 8) * 2;
#pragma unroll
    for (int kk = 0; kk < 8; kk++) {
        int k0 = kk * 16;
        uint32_t a[2][4];
        ldsm_x4(a[0], a_base + k0 * 2);
        ldsm_x4(a[1], a_base + (16 * TP + k0) * 2);
        uint32_t b[4][4];
#pragma unroll
        for (int np = 0; np < 4; np++)
            ldsm_x4(b[np], b_base + (np * 16 * TP + k0) * 2);
#pragma unroll
        for (int mi = 0; mi < 2; mi++)
#pragma unroll
            for (int np = 0; np < 4; np++) {
                mma16816(d[mi][np * 2 + 0], a[mi], &b[np][0]);
                mma16816(d[mi][np * 2 + 1], a[mi], &b[np][2]);
            }
    }
}

// ---- fused gemm k-loop: 32(m) x 64(n), 4 k-steps, all 3 split-passes --------
// fragments loaded ONCE per k-step: 12 ldsm for 48 HMMA (was 18)
__device__ __forceinline__ void mma_fused_g(uint32_t uAh, uint32_t uAl,
                                            uint32_t uBh, uint32_t uBl,
                                            int m_w, int n_w, float d[2][8][4], int lane) {
    uint32_t a_off = ((m_w + (lane & 15)) * SP + (lane >> 4) * 8) * 2;
    int bmi = lane >> 3;
    uint32_t b_off = ((n_w + ((bmi >> 1) * 8) + (lane & 7)) * SP + (bmi & 1) * 8) * 2;
#pragma unroll
    for (int kk = 0; kk < 4; kk++) {
        uint32_t k0 = kk * 32;            // 16 bf16 = 32 bytes
        uint32_t ah[2][4], al[2][4], bh[4][4], bl[4][4];
        ldsm_x4(ah[0], uAh + a_off + k0);
        ldsm_x4(ah[1], uAh + a_off + 16 * SPB + k0);
        ldsm_x4(al[0], uAl + a_off + k0);
        ldsm_x4(al[1], uAl + a_off + 16 * SPB + k0);
#pragma unroll
        for (int np = 0; np < 4; np++) {
            ldsm_x4(bh[np], uBh + b_off + np * 16 * SPB + k0);
            ldsm_x4(bl[np], uBl + b_off + np * 16 * SPB + k0);
        }
#pragma unroll
        for (int mi = 0; mi < 2; mi++)
#pragma unroll
            for (int np = 0; np < 4; np++) {
                mma16816(d[mi][np * 2 + 0], ah[mi], &bh[np][0]);
                mma16816(d[mi][np * 2 + 1], ah[mi], &bh[np][2]);
                mma16816(d[mi][np * 2 + 0], ah[mi], &bl[np][0]);
                mma16816(d[mi][np * 2 + 1], ah[mi], &bl[np][2]);
                mma16816(d[mi][np * 2 + 0], al[mi], &bh[np][0]);
                mma16816(d[mi][np * 2 + 1], al[mi], &bh[np][2]);
            }
    }
}

// cp.async 128-row x 64-col bf16 sub-tile (row length K, col offset kc)
__device__ __forceinline__ void load_sub(const __nv_bfloat16* g, int row0, int K,
                                         int kc, uint32_t dst) {
    int tid = threadIdx.x;
#pragma unroll
    for (int q = 0; q < 4; q++) {
        int idx = q * 256 + tid;          // 128 rows x 8 16B-chunks
        int r = idx >> 3, c = idx & 7;
        cpa16(dst + r * SPB + c * 16, g + (size_t)(row0 + r) * K + kc + c * 8);
    }
}

// cp.async 128x128 bf16 tile (contiguous rows, pitch TP) — adj
__device__ __forceinline__ void load_tile_cpa(const __nv_bfloat16* g, int rowblk,
                                              uint32_t s_u32) {
    const uint4* src = (const uint4*)(g + (size_t)rowblk * 128 * 128);
    int tid = threadIdx.x;
#pragma unroll
    for (int q = 0; q < 8; q++) {
        int idx = q * 256 + tid;
        int r = idx >> 4, c = idx & 15;
        cpa16(s_u32 + r * TP2 + c * 16, src + idx);
    }
}

// ---------------- unified bf16-split HMMA GEMM (128x128, fused passes) -------
__global__ void __launch_bounds__(256, 1)
k_gemm_tc(const __nv_bfloat16* __restrict__ Ah, const __nv_bfloat16* __restrict__ Al,
          const __nv_bfloat16* __restrict__ Bh, const __nv_bfloat16* __restrict__ Bl,
          int K, int Ncols,
          float* __restrict__ Cout,
          int head,
          float* __restrict__ muF, float* __restrict__ lvF,
          const float* __restrict__ bmu, const float* __restrict__ blv,
          __nv_bfloat16* __restrict__ ph, __nv_bfloat16* __restrict__ pl)
{
    extern __shared__ __align__(16) char smem[];
    uint32_t sb = smem_u32(smem);
    // stage layout: [Ah Al Bh Bl] x STILE_B, 2 stages

    int tid = threadIdx.x, wid = tid >> 5, lane = tid & 31;
    int m_w = (wid & 3) * 32, n_w = (wid >> 2) * 64;
    int bm = blockIdx.y * 128, bn = blockIdx.x * 128;

    float d[2][8][4];
#pragma unroll
    for (int mi = 0; mi < 2; mi++)
#pragma unroll
        for (int ni = 0; ni < 8; ni++)
#pragma unroll
            for (int q = 0; q < 4; q++) d[mi][ni][q] = 0.f;

    int nsub = K >> 6;
    load_sub(Ah, bm, K, 0, sb);
    load_sub(Al, bm, K, 0, sb + STILE_B);
    load_sub(Bh, bn, K, 0, sb + 2 * STILE_B);
    load_sub(Bl, bn, K, 0, sb + 3 * STILE_B);
    CP_COMMIT();

    for (int s = 0; s < nsub; s++) {
        int cur = s & 1, nxt = cur ^ 1;
        if (s + 1 < nsub) {
            int kc = (s + 1) << 6;
            uint32_t st = sb + nxt * STAGE_B;
            load_sub(Ah, bm, K, kc, st);
            load_sub(Al, bm, K, kc, st + STILE_B);
            load_sub(Bh, bn, K, kc, st + 2 * STILE_B);
            load_sub(Bl, bn, K, kc, st + 3 * STILE_B);
            CP_COMMIT();
            CP_WAIT1();
        } else {
            CP_WAIT0();
        }
        __syncthreads();
        uint32_t st = sb + cur * STAGE_B;
        mma_fused_g(st, st + STILE_B, st + 2 * STILE_B, st + 3 * STILE_B,
                    m_w, n_w, d, lane);
        __syncthreads();
    }

    int g4 = lane >> 2, tq = lane & 3;
    if (!head) {
#pragma unroll
        for (int mi = 0; mi < 2; mi++) {
            int r0 = bm + m_w + mi * 16 + g4;
#pragma unroll
            for (int ni = 0; ni < 8; ni++) {
                int c = bn + n_w + ni * 8 + tq * 2;
                *(float2*)&Cout[(size_t)r0 * Ncols + c]       = make_float2(d[mi][ni][0], d[mi][ni][1]);
                *(float2*)&Cout[(size_t)(r0 + 8) * Ncols + c] = make_float2(d[mi][ni][2], d[mi][ni][3]);
            }
        }
    } else {
        bool is_mu = (blockIdx.x == 0);
        float* F = is_mu ? muF : lvF;
        const float* bias = is_mu ? bmu : blv;
#pragma unroll
        for (int mi = 0; mi < 2; mi++) {
            int r0 = bm + m_w + mi * 16 + g4;
#pragma unroll
            for (int ni = 0; ni < 8; ni++) {
                int c = n_w + ni * 8 + tq * 2;
                float b0 = bias[c], b1 = bias[c + 1];
                float v00 = d[mi][ni][0] + b0, v01 = d[mi][ni][1] + b1;
                float v10 = d[mi][ni][2] + b0, v11 = d[mi][ni][3] + b1;
                *(float2*)&F[(size_t)r0 * LATD + c]       = make_float2(v00, v01);
                *(float2*)&F[(size_t)(r0 + 8) * LATD + c] = make_float2(v10, v11);
                if (is_mu) {
                    __nv_bfloat16 h0, h1, h2, h3, l0, l1, l2, l3;
                    split1(v00, h0, l0); split1(v01, h1, l1);
                    split1(v10, h2, l2); split1(v11, h3, l3);
                    uint32_t hv0 = ((uint32_t)__bfloat16_as_ushort(h1) << 16) | __bfloat16_as_ushort(h0);
                    uint32_t hv1 = ((uint32_t)__bfloat16_as_ushort(h3) << 16) | __bfloat16_as_ushort(h2);
                    uint32_t lv0 = ((uint32_t)__bfloat16_as_ushort(l1) << 16) | __bfloat16_as_ushort(l0);
                    uint32_t lv1 = ((uint32_t)__bfloat16_as_ushort(l3) << 16) | __bfloat16_as_ushort(l2);
                    *(uint32_t*)&ph[(size_t)r0 * LATD + c]       = hv0;
                    *(uint32_t*)&ph[(size_t)(r0 + 8) * LATD + c] = hv1;
                    *(uint32_t*)&pl[(size_t)r0 * LATD + c]       = lv0;
                    *(uint32_t*)&pl[(size_t)(r0 + 8) * LATD + c] = lv1;
                }
            }
        }
    }
}

// ---------------- adj = sigmoid(mu @ mu^T), cp.async-overlapped --------------
__global__ void __launch_bounds__(256, 2)
k_adj_mma(const __nv_bfloat16* __restrict__ Ah, const __nv_bfloat16* __restrict__ Al,
          float* __restrict__ C)
{
    extern __shared__ __align__(16) char smem[];
    char* sA  = smem;
    char* sBh = smem + TILE_B;
    char* sBl = smem + 2 * TILE_B;
    uint32_t uA = smem_u32(sA), uBh = smem_u32(sBh), uBl = smem_u32(sBl);

    int tid = threadIdx.x, wid = tid >> 5, lane = tid & 31;
    int m_w = (wid & 3) * 32, n_w = (wid >> 2) * 64;

    int t = blockIdx.x, bi = 0;
    while (t >= 64 - bi) { t -= 64 - bi; bi++; }
    int bj = bi + t;

    float d[2][8][4];
#pragma unroll
    for (int mi = 0; mi < 2; mi++)
#pragma unroll
        for (int ni = 0; ni < 8; ni++)
#pragma unroll
            for (int q = 0; q < 4; q++) d[mi][ni][q] = 0.f;

    load_tile_cpa(Ah, bi, uA);
    load_tile_cpa(Ah, bj, uBh);
    load_tile_cpa(Al, bj, uBl);
    CP_COMMIT();
    CP_WAIT0();
    __syncthreads();

    mma_pass_adj(uA, uBl, m_w, n_w, d, lane);
    __syncthreads();
    load_tile_cpa(Al, bi, uBl);
    CP_COMMIT();
    mma_pass_adj(uA, uBh, m_w, n_w, d, lane);
    CP_WAIT0();
    __syncthreads();
    mma_pass_adj(uBl, uBh, m_w, n_w, d, lane);

#pragma unroll
    for (int mi = 0; mi < 2; mi++)
#pragma unroll
        for (int ni = 0; ni < 8; ni++)
#pragma unroll
            for (int q = 0; q < 4; q++)
                d[mi][ni][q] = 1.f / (1.f + __expf(-d[mi][ni][q]));

    int g4 = lane >> 2, tq = lane & 3;

#pragma unroll
    for (int mi = 0; mi < 2; mi++) {
        size_t r0 = (size_t)(bi * 128 + m_w + mi * 16 + g4);
#pragma unroll
        for (int ni = 0; ni < 8; ni++) {
            size_t cc = (size_t)(bj * 128 + n_w + ni * 8 + tq * 2);
            *(float2*)&C[r0 * NN + cc]       = make_float2(d[mi][ni][0], d[mi][ni][1]);
            *(float2*)&C[(r0 + 8) * NN + cc] = make_float2(d[mi][ni][2], d[mi][ni][3]);
        }
    }

    if (bi != bj) {
        __syncthreads();
        float* T = (float*)smem;
#pragma unroll
        for (int mi = 0; mi < 2; mi++) {
            int r = m_w + mi * 16 + g4;
#pragma unroll
            for (int ni = 0; ni < 8; ni++) {
                int c = n_w + ni * 8 + tq * 2;
                T[r * 129 + c]           = d[mi][ni][0];
                T[r * 129 + c + 1]       = d[mi][ni][1];
                T[(r + 8) * 129 + c]     = d[mi][ni][2];
                T[(r + 8) * 129 + c + 1] = d[mi][ni][3];
            }
        }
        __syncthreads();
#pragma unroll
        for (int q = 0; q < 64; q++) {
            int lin = q * 256 + tid;
            int cc = lin >> 7, rr = lin & 127;
            C[(size_t)(bj * 128 + cc) * NN + bi * 128 + rr] = T[rr * 129 + cc];
        }
    }
}

// ---------------- launch ----------------------------------------------------
extern "C" void kernel_launch(void* const* d_in, const int* in_sizes, int n_in,
                              void* d_out, int out_size)
{
    const float* x   = (const float*)d_in[0];
    const int*   ei  = (const int*)d_in[1];
    const float* W1  = (const float*)d_in[2];
    const float* b1  = (const float*)d_in[3];
    const float* W2  = (const float*)d_in[4];
    const float* b2  = (const float*)d_in[5];
    const float* Wmu = (const float*)d_in[6];
    const float* bmu = (const float*)d_in[7];
    const float* Wlv = (const float*)d_in[8];
    const float* blv = (const float*)d_in[9];

    float* out = (float*)d_out;
    float* mu  = out + (size_t)NN * NN;
    float* lv  = mu + (size_t)NN * LATD;

    float *p_hs1, *p_hs2;
    __nv_bfloat16 *p_xh, *p_xl, *p_z1h, *p_z1l, *p_z2h, *p_z2l, *p_muh, *p_mul;
    __nv_bfloat16 *p_w1h, *p_w1l, *p_w2h, *p_w2l, *p_whh, *p_whl;
    cudaGetSymbolAddress((void**)&p_hs1, g_hs1);
    cudaGetSymbolAddress((void**)&p_hs2, g_hs2);
    cudaGetSymbolAddress((void**)&p_xh,  g_xh);
    cudaGetSymbolAddress((void**)&p_xl,  g_xl);
    cudaGetSymbolAddress((void**)&p_z1h, g_z1h);
    cudaGetSymbolAddress((void**)&p_z1l, g_z1l);
    cudaGetSymbolAddress((void**)&p_z2h, g_z2h);
    cudaGetSymbolAddress((void**)&p_z2l, g_z2l);
    cudaGetSymbolAddress((void**)&p_muh, g_muh);
    cudaGetSymbolAddress((void**)&p_mul, g_mul);
    cudaGetSymbolAddress((void**)&p_w1h, g_w1h);
    cudaGetSymbolAddress((void**)&p_w1l, g_w1l);
    cudaGetSymbolAddress((void**)&p_w2h, g_w2h);
    cudaGetSymbolAddress((void**)&p_w2l, g_w2l);
    cudaGetSymbolAddress((void**)&p_whh, g_whh);
    cudaGetSymbolAddress((void**)&p_whl, g_whl);

    cudaFuncSetAttribute(k_adj_mma, cudaFuncAttributeMaxDynamicSharedMemorySize, ADJ_SMEM);
    cudaFuncSetAttribute(k_gemm_tc, cudaFuncAttributeMaxDynamicSharedMemorySize, GEMM_SMEM);

    // 1-3: init, detect+prep, count  (GEMM1 stays launch #4 for ncu)
    k_init   <<<8, 1024>>>();
    k_detprep<<<4896, 256>>>(ei, x, W1, W2, Wmu, Wlv);
    k_count  <<<EE / 256, 256>>>(ei);

    // 4: layer-1 GEMM
    k_gemm_tc<<<dim3(H1D / 128, NN / 128), 256, GEMM_SMEM>>>(
        p_xh, p_xl, p_w1h, p_w1l, DIN, H1D, p_hs1, 0,
        nullptr, nullptr, nullptr, nullptr, nullptr, nullptr);

    // 5-8: scan + CSR fill
    k_scan_a<<<32, 256>>>();
    k_scan_b<<<1, 32>>>();
    k_scan_c<<<32, 256>>>();
    k_fill  <<<EE / 256, 256>>>(ei);

    // 9: agg1 -> z1 planes (relu)
    k_agg<<<NN, H1D>>>(p_hs1, b1, p_z1h, p_z1l, H1D, 1);

    // 10-11: layer-2 GEMM + agg2
    k_gemm_tc<<<dim3(LATD / 128, NN / 128), 256, GEMM_SMEM>>>(
        p_z1h, p_z1l, p_w2h, p_w2l, H1D, LATD, p_hs2, 0,
        nullptr, nullptr, nullptr, nullptr, nullptr, nullptr);
    k_agg<<<NN, LATD>>>(p_hs2, b2, p_z2h, p_z2l, LATD, 0);

    // 12: fused heads
    k_gemm_tc<<<dim3(2, NN / 128), 256, GEMM_SMEM>>>(
        p_z2h, p_z2l, p_whh, p_whl, LATD, 2 * LATD, nullptr, 1,
        mu, lv, bmu, blv, p_muh, p_mul);

    // 13: adj = sigmoid(mu @ mu^T)
    k_adj_mma<<<2080, 256, ADJ_SMEM>>>(p_muh, p_mul, out);
}